// round 1
// baseline (speedup 1.0000x reference)
#include <cuda_runtime.h>
#include <cstdint>

#define C 128
#define K2 9
#define H 5
#define KDIM (K2 * C)     // 1152
#define NCOLS (H * C)     // 640
#define MPAD 40064        // 313 * 128, covers N=40000
#define EPS 1e-5f

// ---- scratch (allocation-free: static device globals) ----
__device__ float g_Y[(size_t)H * MPAD * C];   // ~102.6 MB
__device__ float g_sum[NCOLS];
__device__ float g_sumsq[NCOLS];
__device__ float g_scale[NCOLS];
__device__ float g_bias[NCOLS];

// ---- helpers ----
__device__ __forceinline__ unsigned f2tf32(float x) {
    unsigned r;
    asm("cvt.rna.tf32.f32 %0, %1;" : "=r"(r) : "f"(x));
    return r;
}

__device__ __forceinline__ void mma8(float* d, const unsigned* a, const unsigned* b) {
    asm volatile(
        "mma.sync.aligned.m16n8k8.row.col.f32.tf32.tf32.f32 "
        "{%0,%1,%2,%3}, {%4,%5,%6,%7}, {%8,%9}, {%0,%1,%2,%3};\n"
        : "+f"(d[0]), "+f"(d[1]), "+f"(d[2]), "+f"(d[3])
        : "r"(a[0]), "r"(a[1]), "r"(a[2]), "r"(a[3]),
          "r"(b[0]), "r"(b[1]));
}

__device__ __forceinline__ void cp16(void* smem, const void* g) {
    unsigned sa = (unsigned)__cvta_generic_to_shared(smem);
    asm volatile("cp.async.cg.shared.global [%0], [%1], 16;\n" :: "r"(sa), "l"(g));
}
#define CP_COMMIT asm volatile("cp.async.commit_group;\n" ::: "memory")
#define CP_WAIT(n) asm volatile("cp.async.wait_group %0;\n" :: "n"(n) : "memory")

// ---- kernel 0: zero stats accumulators (graph-replay deterministic) ----
__global__ void zero_kernel() {
    int t = blockIdx.x * blockDim.x + threadIdx.x;
    if (t < NCOLS) { g_sum[t] = 0.f; g_sumsq[t] = 0.f; }
}

// ---- kernel 1: fused gather + TF32 GEMM  Y[h][n][c] ----
// CTA tile 128x128, warps 2x4 (each 64x32), K staged 16 at a time, double buffered.
__global__ __launch_bounds__(256, 2)
void gemm_kernel(const float* __restrict__ feats, const int* __restrict__ nbr,
                 const float* __restrict__ W1, int N) {
    __shared__ float As[2][128][20];    // pitch 20: conflict-free frag loads, 16B-aligned rows
    __shared__ float Bs[2][16][136];    // pitch 136: conflict-free frag loads
    __shared__ int idxs[128 * 9];

    const int tid = threadIdx.x;
    const int m0 = blockIdx.x * 128;
    const int h = blockIdx.y;

    for (int i = tid; i < 128 * 9; i += 256) {
        int r = i / 9, k = i - r * 9;
        int n = m0 + r;
        idxs[i] = (n < N) ? nbr[n * 9 + k] : 0;
    }
    __syncthreads();

    const int KT = KDIM / 16;  // 72

    auto load_stage = [&](int kt, int s) {
        int tap = kt >> 3;             // which 3x3 tap (16 | 128)
        int c0 = (kt & 7) << 4;        // channel offset within tap
        // A: 128 rows x 16 floats = 512 x 16B chunks (gathered from feats)
        #pragma unroll
        for (int j = 0; j < 2; j++) {
            int q = tid + j * 256;
            int r = q >> 2, cc = (q & 3) << 2;
            const float* src = feats + (size_t)idxs[r * 9 + tap] * C + c0 + cc;
            cp16(&As[s][r][cc], src);
        }
        // B: 16 rows x 128 floats = 512 x 16B chunks (from W1[h][tap][c][:])
        #pragma unroll
        for (int j = 0; j < 2; j++) {
            int q = tid + j * 256;
            int r = q >> 5, d = (q & 31) << 2;
            const float* src = W1 + ((((size_t)h * K2 + tap) * C + (c0 + r)) * C + d);
            cp16(&Bs[s][r][d], src);
        }
    };

    float acc[4][4][4];
    #pragma unroll
    for (int i = 0; i < 4; i++)
        #pragma unroll
        for (int j = 0; j < 4; j++)
            #pragma unroll
            for (int e = 0; e < 4; e++) acc[i][j][e] = 0.f;

    const int warp = tid >> 5, lane = tid & 31;
    const int wm = (warp >> 2) * 64;   // 0 or 64
    const int wn = (warp & 3) * 32;    // 0,32,64,96

    load_stage(0, 0);
    CP_COMMIT;

    for (int kt = 0; kt < KT; kt++) {
        int s = kt & 1;
        if (kt + 1 < KT) { load_stage(kt + 1, s ^ 1); CP_COMMIT; CP_WAIT(1); }
        else { CP_WAIT(0); }
        __syncthreads();

        #pragma unroll
        for (int ks = 0; ks < 2; ks++) {
            unsigned af[4][4], bf[4][2];
            int ac = ks * 8 + (lane & 3);
            int ar = wm + (lane >> 2);
            #pragma unroll
            for (int i = 0; i < 4; i++) {
                af[i][0] = f2tf32(As[s][ar + i * 16][ac]);
                af[i][1] = f2tf32(As[s][ar + i * 16 + 8][ac]);
                af[i][2] = f2tf32(As[s][ar + i * 16][ac + 4]);
                af[i][3] = f2tf32(As[s][ar + i * 16 + 8][ac + 4]);
            }
            int br = ks * 8 + (lane & 3);
            int bc = wn + (lane >> 2);
            #pragma unroll
            for (int j = 0; j < 4; j++) {
                bf[j][0] = f2tf32(Bs[s][br][bc + j * 8]);
                bf[j][1] = f2tf32(Bs[s][br + 4][bc + j * 8]);
            }
            #pragma unroll
            for (int i = 0; i < 4; i++)
                #pragma unroll
                for (int j = 0; j < 4; j++)
                    mma8(acc[i][j], af[i], bf[j]);
        }
        __syncthreads();
    }

    // epilogue: write Y tile (rows beyond N land in pad region, ignored later)
    float* Yh = g_Y + (size_t)h * MPAD * C;
    #pragma unroll
    for (int i = 0; i < 4; i++) {
        int r0 = m0 + wm + i * 16 + (lane >> 2);
        #pragma unroll
        for (int j = 0; j < 4; j++) {
            int cb = wn + j * 8 + (lane & 3) * 2;
            *(float2*)(Yh + (size_t)r0 * C + cb) = make_float2(acc[i][j][0], acc[i][j][1]);
            *(float2*)(Yh + (size_t)(r0 + 8) * C + cb) = make_float2(acc[i][j][2], acc[i][j][3]);
        }
    }
}

// ---- kernel 2: per-(h,c) sum / sumsq partial reduction ----
__global__ __launch_bounds__(256)
void stats_kernel(int N) {
    int h = blockIdx.x;
    int chunk = (N + gridDim.y - 1) / gridDim.y;
    int n0 = blockIdx.y * chunk;
    int n1 = min(n0 + chunk, N);
    int tid = threadIdx.x;
    int c = tid & 127;
    int rofs = tid >> 7;
    const float* Yh = g_Y + (size_t)h * MPAD * C;
    float s = 0.f, q = 0.f;
    for (int n = n0 + rofs; n < n1; n += 2) {
        float v = Yh[(size_t)n * C + c];
        s += v;
        q += v * v;
    }
    __shared__ float sh[256], shq[256];
    sh[tid] = s; shq[tid] = q;
    __syncthreads();
    if (tid < 128) {
        atomicAdd(&g_sum[h * C + tid], sh[tid] + sh[tid + 128]);
        atomicAdd(&g_sumsq[h * C + tid], shq[tid] + shq[tid + 128]);
    }
}

// ---- kernel 3: finalize BN affine ----
__global__ void finalize_kernel(const float* __restrict__ gamma,
                                const float* __restrict__ beta, int N) {
    int t = blockIdx.x * blockDim.x + threadIdx.x;
    if (t < NCOLS) {
        float inv = 1.f / (float)N;
        float mean = g_sum[t] * inv;
        float var = g_sumsq[t] * inv - mean * mean;
        float sc = gamma[t] * rsqrtf(var + EPS);
        g_scale[t] = sc;
        g_bias[t] = beta[t] - mean * sc;
    }
}

// ---- kernel 4: BN + ReLU + per-head 1x1 conv + concat ----
__global__ __launch_bounds__(256)
void head_kernel(const float* __restrict__ w0, const float* __restrict__ b0,
                 const float* __restrict__ w1, const float* __restrict__ b1,
                 const float* __restrict__ w2, const float* __restrict__ b2,
                 const float* __restrict__ w3, const float* __restrict__ b3,
                 const float* __restrict__ w4, const float* __restrict__ b4,
                 float* __restrict__ out, int N) {
    __shared__ float Ys[64 * 129];
    int n0 = blockIdx.x * 64;
    int tid = threadIdx.x;
    const float* W[H] = {w0, w1, w2, w3, w4};
    const float* B[H] = {b0, b1, b2, b3, b4};
    const int OC[H] = {3, 2, 1, 3, 2};
    const int OFF[H] = {0, 3, 5, 6, 9};

    #pragma unroll
    for (int h = 0; h < H; h++) {
        const float* Yh = g_Y + (size_t)h * MPAD * C;
        for (int i = tid; i < 64 * C; i += 256) {
            int r = i >> 7, c = i & 127;
            int n = n0 + r;
            float v = 0.f;
            if (n < N) {
                v = Yh[(size_t)n * C + c];
                v = fmaxf(v * g_scale[h * C + c] + g_bias[h * C + c], 0.f);
            }
            Ys[r * 129 + c] = v;
        }
        __syncthreads();
        const int oc = OC[h];
        for (int o = tid; o < 64 * oc; o += 256) {
            int r = o / oc, jj = o - r * oc;
            int n = n0 + r;
            if (n < N) {
                float a = B[h][jj];
                const float* wp = W[h];
                #pragma unroll 8
                for (int c = 0; c < C; c++)
                    a += Ys[r * 129 + c] * wp[c * oc + jj];
                out[(size_t)n * 11 + OFF[h] + jj] = a;
            }
        }
        __syncthreads();
    }
}

extern "C" void kernel_launch(void* const* d_in, const int* in_sizes, int n_in,
                              void* d_out, int out_size) {
    const float* feats   = (const float*)d_in[0];
    const int*   nbr     = (const int*)d_in[1];
    const float* W1      = (const float*)d_in[2];
    const float* gamma   = (const float*)d_in[3];
    const float* beta    = (const float*)d_in[4];
    const float* w_hm    = (const float*)d_in[5];
    const float* b_hm    = (const float*)d_in[6];
    const float* w_ctr   = (const float*)d_in[7];
    const float* b_ctr   = (const float*)d_in[8];
    const float* w_cz    = (const float*)d_in[9];
    const float* b_cz    = (const float*)d_in[10];
    const float* w_dim   = (const float*)d_in[11];
    const float* b_dim   = (const float*)d_in[12];
    const float* w_rot   = (const float*)d_in[13];
    const float* b_rot   = (const float*)d_in[14];
    float* out = (float*)d_out;

    int N = in_sizes[0] / C;
    int MT = (N + 127) / 128;

    zero_kernel<<<(NCOLS + 255) / 256, 256>>>();
    gemm_kernel<<<dim3(MT, H), 256>>>(feats, nbr, W1, N);
    stats_kernel<<<dim3(H, 64), 256>>>(N);
    finalize_kernel<<<(NCOLS + 255) / 256, 256>>>(gamma, beta, N);
    head_kernel<<<(N + 63) / 64, 256>>>(w_hm, b_hm, w_ctr, b_ctr, w_cz, b_cz,
                                        w_dim, b_dim, w_rot, b_rot, out, N);
}

// round 3
// speedup vs baseline: 1.0332x; 1.0332x over previous
#include <cuda_runtime.h>
#include <cstdint>

#define C 128
#define K2 9
#define H 5
#define KDIM 1152
#define NCOLS 640
#define MPAD 40064       // 313 * 128
#define MT_TILES 313
#define KC 36            // K chunks of 32
#define STAGES 5
#define EPS 1e-5f

// A tile image: 128 rows x 36 words (pitch 36 for conflict-free LDS), 18432 B
#define A_PITCH 36
#define A_IMG_W (128 * A_PITCH)          // words
#define A_IMG_B (A_IMG_W * 4)            // 18432
// B tile image: 32 rows x 136 words (pitch 136), 17408 B
#define B_PITCH 136
#define B_IMG_W (32 * B_PITCH)
#define B_IMG_B (B_IMG_W * 4)            // 17408
#define GEMM_SMEM (STAGES * (A_IMG_B + B_IMG_B))   // 179200

// ---- device-global scratch (allocation-free) ----
__device__ float g_G[(size_t)MT_TILES * KC * A_IMG_W];  // im2col images (~207 MB)
__device__ float g_Wt[(size_t)H * KC * B_IMG_W];        // weight images (~3.1 MB)
__device__ float g_Y[(size_t)MPAD * NCOLS];             // pre-BN activations (~102.6 MB)
__device__ float g_sum[NCOLS];
__device__ float g_sumsq[NCOLS];
__device__ float g_scale[NCOLS];
__device__ float g_bias[NCOLS];

// ---- helpers ----
__device__ __forceinline__ float tf32r(float x) {
    unsigned u;
    asm("cvt.rna.tf32.f32 %0, %1;" : "=r"(u) : "f"(x));
    return __uint_as_float(u);
}
__device__ __forceinline__ uint32_t smem_u32(const void* p) {
    uint32_t a;
    asm("{ .reg .u64 t; cvta.to.shared.u64 t, %1; cvt.u32.u64 %0, t; }" : "=r"(a) : "l"(p));
    return a;
}
__device__ __forceinline__ void mma8(float* d, const unsigned* a, const unsigned* b) {
    asm volatile(
        "mma.sync.aligned.m16n8k8.row.col.f32.tf32.tf32.f32 "
        "{%0,%1,%2,%3}, {%4,%5,%6,%7}, {%8,%9}, {%0,%1,%2,%3};\n"
        : "+f"(d[0]), "+f"(d[1]), "+f"(d[2]), "+f"(d[3])
        : "r"(a[0]), "r"(a[1]), "r"(a[2]), "r"(a[3]),
          "r"(b[0]), "r"(b[1]));
}
__device__ __forceinline__ void bulk_g2s(uint32_t dst, const void* src, uint32_t bytes, uint32_t mbar) {
    asm volatile(
        "cp.async.bulk.shared::cluster.global.mbarrier::complete_tx::bytes [%0], [%1], %2, [%3];"
        :: "r"(dst), "l"(src), "r"(bytes), "r"(mbar) : "memory");
}
#define MBAR_INIT(a, n) asm volatile("mbarrier.init.shared.b64 [%0], %1;" :: "r"(a), "r"(n) : "memory")
#define MBAR_EXPECT(a, n) asm volatile("mbarrier.arrive.expect_tx.shared.b64 _, [%0], %1;" :: "r"(a), "r"(n) : "memory")

__device__ __forceinline__ void mbar_wait(uint32_t mbar, uint32_t parity) {
    asm volatile(
        "{\n\t.reg .pred P1;\n\t"
        "WAIT_LOOP_%=:\n\t"
        "mbarrier.try_wait.parity.acquire.cta.shared::cta.b64 P1, [%0], %1, 0x989680;\n\t"
        "@P1 bra.uni WAIT_DONE_%=;\n\t"
        "bra.uni WAIT_LOOP_%=;\n\t"
        "WAIT_DONE_%=:\n\t}"
        :: "r"(mbar), "r"(parity) : "memory");
}

// ---- weight prep: transpose + tf32-round into B tile images ----
__global__ void wprep_kernel(const float* __restrict__ W1) {
    int i = blockIdx.x * 256 + threadIdx.x;
    if (i >= H * KDIM * C) return;
    int n = i & 127;             // output col
    int k = (i >> 7) % KDIM;
    int h = i / (KDIM * C);
    int tap = k >> 7, cin = k & 127;
    float val = tf32r(W1[(((size_t)h * K2 + tap) * C + cin) * C + n]);
    g_Wt[((size_t)(h * KC + (k >> 5))) * B_IMG_W + (k & 31) * B_PITCH + n] = val;
}

// ---- gather: im2col rows into A tile images (tf32-rounded) ----
__global__ __launch_bounds__(256) void gather_kernel(const float* __restrict__ feats,
                                                     const int* __restrict__ nbr, int N) {
    int w = blockIdx.x * 8 + (threadIdx.x >> 5);
    int lane = threadIdx.x & 31;
    if (w >= N * K2) return;
    int n = w / K2, tap = w - n * K2;
    int idx = __ldg(&nbr[w]);
    float4 v = *(const float4*)(feats + (size_t)idx * C + lane * 4);
    v.x = tf32r(v.x); v.y = tf32r(v.y); v.z = tf32r(v.z); v.w = tf32r(v.w);
    size_t img = (size_t)((n >> 7) * KC + tap * 4 + (lane >> 3)) * A_IMG_W;
    *(float4*)(g_G + img + (n & 127) * A_PITCH + (lane & 7) * 4) = v;
}

// ---- zero stats + pad rows of the last A tile ----
__global__ void zero_kernel(int N) {
    int t = blockIdx.x * blockDim.x + threadIdx.x;
    if (t < 2 * NCOLS) {
        if (t < NCOLS) g_sum[t] = 0.f; else g_sumsq[t - NCOLS] = 0.f;
        return;
    }
    int i = t - 2 * NCOLS;
    int padrows = MPAD - N;                    // 64
    int total = padrows * KC * A_PITCH;
    if (i < total) {
        int kc = i / (padrows * A_PITCH);
        int rem = i - kc * padrows * A_PITCH;
        int r = (N & 127) + rem / A_PITCH;
        int cw = rem % A_PITCH;
        g_G[(size_t)((MT_TILES - 1) * KC + kc) * A_IMG_W + r * A_PITCH + cw] = 0.f;
    }
}

// ---- GEMM: bulk-async pipeline + mma.sync TF32 + fused stats ----
__global__ __launch_bounds__(256, 1) void gemm_kernel() {
    extern __shared__ float sm[];
    __shared__ __align__(8) unsigned long long mbars[STAGES];

    const int tid = threadIdx.x;
    const int h = blockIdx.x;
    const int mt = blockIdx.y;
    const int warp = tid >> 5, lane = tid & 31;
    const int wm = (warp >> 2) * 64;   // 0 or 64
    const int wn = (warp & 3) * 32;    // 0,32,64,96

    uint32_t mb = smem_u32(mbars);
    uint32_t smb = smem_u32(sm);
    if (tid == 0) {
        #pragma unroll
        for (int i = 0; i < STAGES; i++) MBAR_INIT(mb + i * 8, 1);
    }
    __syncthreads();

    const float* Gt = g_G + (size_t)mt * KC * A_IMG_W;
    const float* Bt = g_Wt + (size_t)h * KC * B_IMG_W;

    auto issue = [&](int s) {
        int slot = s % STAGES;
        uint32_t full = mb + slot * 8;
        MBAR_EXPECT(full, A_IMG_B + B_IMG_B);
        bulk_g2s(smb + slot * A_IMG_B, Gt + (size_t)s * A_IMG_W, A_IMG_B, full);
        bulk_g2s(smb + STAGES * A_IMG_B + slot * B_IMG_B, Bt + (size_t)s * B_IMG_W, B_IMG_B, full);
    };

    if (tid == 0) {
        #pragma unroll
        for (int s = 0; s < STAGES - 1; s++) issue(s);
    }

    float acc[4][4][4];
    #pragma unroll
    for (int i = 0; i < 4; i++)
        #pragma unroll
        for (int j = 0; j < 4; j++)
            #pragma unroll
            for (int e = 0; e < 4; e++) acc[i][j][e] = 0.f;

    int slot = 0, ph = 0;
    for (int s = 0; s < KC; s++) {
        mbar_wait(mb + slot * 8, ph);
        const float* As = sm + slot * (A_IMG_B / 4);
        const float* Bs = sm + STAGES * (A_IMG_B / 4) + slot * (B_IMG_B / 4);

        #pragma unroll
        for (int ks = 0; ks < 4; ks++) {
            unsigned af[4][4], bf[4][2];
            int ac = ks * 8 + (lane & 3);
            int ar = wm + (lane >> 2);
            #pragma unroll
            for (int i = 0; i < 4; i++) {
                af[i][0] = __float_as_uint(As[(ar + i * 16) * A_PITCH + ac]);
                af[i][1] = __float_as_uint(As[(ar + i * 16 + 8) * A_PITCH + ac]);
                af[i][2] = __float_as_uint(As[(ar + i * 16) * A_PITCH + ac + 4]);
                af[i][3] = __float_as_uint(As[(ar + i * 16 + 8) * A_PITCH + ac + 4]);
            }
            int br = ks * 8 + (lane & 3);
            int bc = wn + (lane >> 2);
            #pragma unroll
            for (int j = 0; j < 4; j++) {
                bf[j][0] = __float_as_uint(Bs[br * B_PITCH + bc + j * 8]);
                bf[j][1] = __float_as_uint(Bs[(br + 4) * B_PITCH + bc + j * 8]);
            }
            #pragma unroll
            for (int i = 0; i < 4; i++)
                #pragma unroll
                for (int j = 0; j < 4; j++)
                    mma8(acc[i][j], af[i], bf[j]);
        }
        __syncthreads();
        if (tid == 0 && s + STAGES - 1 < KC) issue(s + STAGES - 1);
        if (++slot == STAGES) { slot = 0; ph ^= 1; }
    }

    // ---- epilogue: write Y + fused column stats ----
    float* Yrow = g_Y + (size_t)(mt * 128) * NCOLS + h * 128;
    #pragma unroll
    for (int i = 0; i < 4; i++) {
        int r0 = wm + i * 16 + (lane >> 2);
        #pragma unroll
        for (int j = 0; j < 4; j++) {
            int cb = wn + j * 8 + (lane & 3) * 2;
            *(float2*)(Yrow + (size_t)r0 * NCOLS + cb) = make_float2(acc[i][j][0], acc[i][j][1]);
            *(float2*)(Yrow + (size_t)(r0 + 8) * NCOLS + cb) = make_float2(acc[i][j][2], acc[i][j][3]);
        }
    }

    // column partial sums: each thread covers 8 columns (4 j-tiles x 2)
    #pragma unroll
    for (int j = 0; j < 4; j++) {
        #pragma unroll
        for (int e = 0; e < 2; e++) {
            float s = 0.f, q = 0.f;
            #pragma unroll
            for (int i = 0; i < 4; i++) {
                float v0 = acc[i][j][e], v1 = acc[i][j][e + 2];
                s += v0 + v1;
                q += v0 * v0 + v1 * v1;
            }
            // reduce across the 8 threads sharing this column (lanes differing in bits 2..4)
            #pragma unroll
            for (int m = 16; m >= 4; m >>= 1) {
                s += __shfl_xor_sync(0xffffffffu, s, m);
                q += __shfl_xor_sync(0xffffffffu, q, m);
            }
            if ((lane >> 2) == 0) {
                int col = h * 128 + wn + j * 8 + (lane & 3) * 2 + e;
                atomicAdd(&g_sum[col], s);
                atomicAdd(&g_sumsq[col], q);
            }
        }
    }
}

__global__ void finalize_kernel(const float* __restrict__ gamma,
                                const float* __restrict__ beta, int N) {
    int t = blockIdx.x * blockDim.x + threadIdx.x;
    if (t < NCOLS) {
        float inv = 1.f / (float)N;
        float mean = g_sum[t] * inv;
        float var = g_sumsq[t] * inv - mean * mean;
        float sc = gamma[t] * rsqrtf(var + EPS);
        g_scale[t] = sc;
        g_bias[t] = beta[t] - mean * sc;
    }
}

// ---- BN + ReLU + per-head 1x1 conv + concat ----
__global__ __launch_bounds__(256) void head_kernel(
    const float* __restrict__ w0, const float* __restrict__ b0,
    const float* __restrict__ w1, const float* __restrict__ b1,
    const float* __restrict__ w2, const float* __restrict__ b2,
    const float* __restrict__ w3, const float* __restrict__ b3,
    const float* __restrict__ w4, const float* __restrict__ b4,
    float* __restrict__ out, int N) {
    __shared__ float Ys[64 * 129];
    int n0 = blockIdx.x * 64;
    int tid = threadIdx.x;
    const float* W[H] = {w0, w1, w2, w3, w4};
    const float* B[H] = {b0, b1, b2, b3, b4};
    const int OC[H] = {3, 2, 1, 3, 2};
    const int OFF[H] = {0, 3, 5, 6, 9};

    #pragma unroll
    for (int h = 0; h < H; h++) {
        for (int i = tid; i < 64 * C; i += 256) {
            int r = i >> 7, c = i & 127;
            int n = n0 + r;
            float v = 0.f;
            if (n < N) {
                v = g_Y[(size_t)n * NCOLS + h * 128 + c];
                v = fmaxf(v * g_scale[h * 128 + c] + g_bias[h * 128 + c], 0.f);
            }
            Ys[r * 129 + c] = v;
        }
        __syncthreads();
        const int oc = OC[h];
        for (int o = tid; o < 64 * oc; o += 256) {
            int r = o / oc, jj = o - r * oc;
            int n = n0 + r;
            if (n < N) {
                float a = B[h][jj];
                const float* wp = W[h];
                #pragma unroll 8
                for (int c = 0; c < C; c++)
                    a += Ys[r * 129 + c] * wp[c * oc + jj];
                out[(size_t)n * 11 + OFF[h] + jj] = a;
            }
        }
        __syncthreads();
    }
}

extern "C" void kernel_launch(void* const* d_in, const int* in_sizes, int n_in,
                              void* d_out, int out_size) {
    const float* feats = (const float*)d_in[0];
    const int*   nbr   = (const int*)d_in[1];
    const float* W1    = (const float*)d_in[2];
    const float* gamma = (const float*)d_in[3];
    const float* beta  = (const float*)d_in[4];
    float* out = (float*)d_out;

    int N = in_sizes[0] / C;
    int MT = (N + 127) / 128;

    static int configured = 0;
    cudaFuncSetAttribute(gemm_kernel, cudaFuncAttributeMaxDynamicSharedMemorySize, GEMM_SMEM);
    (void)configured;

    wprep_kernel<<<(H * KDIM * C + 255) / 256, 256>>>(W1);
    gather_kernel<<<(N * K2 + 7) / 8, 256>>>(feats, nbr, N);
    {
        int zpad = 2 * NCOLS + (MPAD - N) * KC * A_PITCH;
        zero_kernel<<<(zpad + 255) / 256, 256>>>(N);
    }
    gemm_kernel<<<dim3(H, MT), 256, GEMM_SMEM>>>();
    finalize_kernel<<<(NCOLS + 255) / 256, 256>>>(gamma, beta, N);
    head_kernel<<<(N + 63) / 64, 256>>>(
        (const float*)d_in[5], (const float*)d_in[6],
        (const float*)d_in[7], (const float*)d_in[8],
        (const float*)d_in[9], (const float*)d_in[10],
        (const float*)d_in[11], (const float*)d_in[12],
        (const float*)d_in[13], (const float*)d_in[14], out, N);
}

// round 4
// speedup vs baseline: 1.1080x; 1.0724x over previous
#include <cuda_runtime.h>
#include <cstdint>

#define C 128
#define K2 9
#define H 5
#define KDIM 1152
#define NCOLS 640
#define MT_MAX 157           // tiles of 256 rows, covers N<=40192
#define MPAD (MT_MAX * 256)
#define KC 36                // K chunks of 32
#define STAGES 4
#define EPS 1e-5f

// A tile image: 256 rows x 36 words (pitch 36, conflict-free LDS), 36864 B
#define A_PITCH 36
#define A_IMG_W (256 * A_PITCH)
#define A_IMG_B (A_IMG_W * 4)            // 36864
// B tile image: 32 rows x 136 words (pitch 136), 17408 B
#define B_PITCH 136
#define B_IMG_W (32 * B_PITCH)
#define B_IMG_B (B_IMG_W * 4)
#define GEMM_SMEM (STAGES * (A_IMG_B + B_IMG_B))   // 217088

// ---- device-global scratch (allocation-free) ----
__device__ float g_G[(size_t)MT_MAX * KC * A_IMG_W];   // im2col images (~208 MB)
__device__ float g_Wt[(size_t)H * KC * B_IMG_W];       // weight images (~3.1 MB)
__device__ float g_Y[(size_t)MPAD * NCOLS];            // pre-BN activations (~103 MB)
__device__ float g_sum[NCOLS];
__device__ float g_sumsq[NCOLS];

// ---- helpers ----
__device__ __forceinline__ float tf32r(float x) {
    unsigned u;
    asm("cvt.rna.tf32.f32 %0, %1;" : "=r"(u) : "f"(x));
    return __uint_as_float(u);
}
__device__ __forceinline__ uint32_t smem_u32(const void* p) {
    uint32_t a;
    asm("{ .reg .u64 t; cvta.to.shared.u64 t, %1; cvt.u32.u64 %0, t; }" : "=r"(a) : "l"(p));
    return a;
}
__device__ __forceinline__ void mma8(float* d, const unsigned* a, const unsigned* b) {
    asm volatile(
        "mma.sync.aligned.m16n8k8.row.col.f32.tf32.tf32.f32 "
        "{%0,%1,%2,%3}, {%4,%5,%6,%7}, {%8,%9}, {%0,%1,%2,%3};\n"
        : "+f"(d[0]), "+f"(d[1]), "+f"(d[2]), "+f"(d[3])
        : "r"(a[0]), "r"(a[1]), "r"(a[2]), "r"(a[3]),
          "r"(b[0]), "r"(b[1]));
}
__device__ __forceinline__ void bulk_g2s(uint32_t dst, const void* src, uint32_t bytes, uint32_t mbar) {
    asm volatile(
        "cp.async.bulk.shared::cluster.global.mbarrier::complete_tx::bytes [%0], [%1], %2, [%3];"
        :: "r"(dst), "l"(src), "r"(bytes), "r"(mbar) : "memory");
}
#define MBAR_INIT(a, n) asm volatile("mbarrier.init.shared.b64 [%0], %1;" :: "r"(a), "r"(n) : "memory")
#define MBAR_EXPECT(a, n) asm volatile("mbarrier.arrive.expect_tx.shared.b64 _, [%0], %1;" :: "r"(a), "r"(n) : "memory")

__device__ __forceinline__ void mbar_wait(uint32_t mbar, uint32_t parity) {
    asm volatile(
        "{\n\t.reg .pred P1;\n\t"
        "WAIT_LOOP_%=:\n\t"
        "mbarrier.try_wait.parity.acquire.cta.shared::cta.b64 P1, [%0], %1, 0x989680;\n\t"
        "@P1 bra.uni WAIT_DONE_%=;\n\t"
        "bra.uni WAIT_LOOP_%=;\n\t"
        "WAIT_DONE_%=:\n\t}"
        :: "r"(mbar), "r"(parity) : "memory");
}

// ---- prep: weight transpose/round + stats zero + A-image pad zero ----
#define WPREP_TOTAL (H * KDIM * C)
__global__ void prep_kernel(const float* __restrict__ W1, int N, int MT) {
    int gi = blockIdx.x * 256 + threadIdx.x;
    if (gi < WPREP_TOTAL) {
        int n = gi & 127;
        int k = (gi >> 7) % KDIM;
        int h = gi / (KDIM * C);
        int tap = k >> 7, cin = k & 127;
        float val = tf32r(W1[(((size_t)h * K2 + tap) * C + cin) * C + n]);
        g_Wt[((size_t)(h * KC + (k >> 5))) * B_IMG_W + (k & 31) * B_PITCH + n] = val;
        return;
    }
    int j = gi - WPREP_TOTAL;
    if (j < 2 * NCOLS) {
        if (j < NCOLS) g_sum[j] = 0.f; else g_sumsq[j - NCOLS] = 0.f;
        return;
    }
    int i = j - 2 * NCOLS;
    int padrows = MT * 256 - N;
    int total = padrows * KC * A_PITCH;
    if (i < total && padrows > 0) {
        int kc = i / (padrows * A_PITCH);
        int rem = i - kc * padrows * A_PITCH;
        int r = (N & 255) + rem / A_PITCH;
        int cw = rem % A_PITCH;
        g_G[(size_t)((MT - 1) * KC + kc) * A_IMG_W + r * A_PITCH + cw] = 0.f;
    }
}

// ---- gather: im2col rows into A tile images (tf32-rounded) ----
__global__ __launch_bounds__(256) void gather_kernel(const float* __restrict__ feats,
                                                     const int* __restrict__ nbr, int N) {
    int w = blockIdx.x * 8 + (threadIdx.x >> 5);
    int lane = threadIdx.x & 31;
    if (w >= N * K2) return;
    int n = w / K2, tap = w - n * K2;
    int idx = __ldg(&nbr[w]);
    float4 v = *(const float4*)(feats + (size_t)idx * C + lane * 4);
    v.x = tf32r(v.x); v.y = tf32r(v.y); v.z = tf32r(v.z); v.w = tf32r(v.w);
    size_t img = (size_t)((n >> 8) * KC + tap * 4 + (lane >> 3)) * A_IMG_W;
    *(float4*)(g_G + img + (n & 255) * A_PITCH + (lane & 7) * 4) = v;
}

// ---- GEMM: 256x128 CTA tile, 64x64 warp tiles, bulk-async pipeline, fused stats ----
__global__ __launch_bounds__(256, 1) void gemm_kernel() {
    extern __shared__ float sm[];
    __shared__ __align__(8) unsigned long long mbars[STAGES];

    const int tid = threadIdx.x;
    const int h = blockIdx.x;
    const int mt = blockIdx.y;
    const int warp = tid >> 5, lane = tid & 31;
    const int wm = (warp >> 1) * 64;   // 0,64,128,192
    const int wn = (warp & 1) * 64;    // 0,64

    uint32_t mb = smem_u32(mbars);
    uint32_t smb = smem_u32(sm);
    if (tid == 0) {
        #pragma unroll
        for (int i = 0; i < STAGES; i++) MBAR_INIT(mb + i * 8, 1);
    }
    __syncthreads();

    const float* Gt = g_G + (size_t)mt * KC * A_IMG_W;
    const float* Bt = g_Wt + (size_t)h * KC * B_IMG_W;

    auto issue = [&](int s) {
        int slot = s % STAGES;
        uint32_t full = mb + slot * 8;
        MBAR_EXPECT(full, A_IMG_B + B_IMG_B);
        bulk_g2s(smb + slot * A_IMG_B, Gt + (size_t)s * A_IMG_W, A_IMG_B, full);
        bulk_g2s(smb + STAGES * A_IMG_B + slot * B_IMG_B, Bt + (size_t)s * B_IMG_W, B_IMG_B, full);
    };

    if (tid == 0) {
        #pragma unroll
        for (int s = 0; s < STAGES - 1; s++) issue(s);
    }

    float acc[4][8][4];
    #pragma unroll
    for (int i = 0; i < 4; i++)
        #pragma unroll
        for (int j = 0; j < 8; j++)
            #pragma unroll
            for (int e = 0; e < 4; e++) acc[i][j][e] = 0.f;

    int slot = 0, ph = 0;
    for (int s = 0; s < KC; s++) {
        mbar_wait(mb + slot * 8, ph);
        const float* As = sm + slot * (A_IMG_B / 4);
        const float* Bs = sm + STAGES * (A_IMG_B / 4) + slot * (B_IMG_B / 4);

        #pragma unroll
        for (int ks = 0; ks < 4; ks++) {
            unsigned af[4][4], bf[8][2];
            int ac = ks * 8 + (lane & 3);
            int ar = wm + (lane >> 2);
            #pragma unroll
            for (int i = 0; i < 4; i++) {
                af[i][0] = __float_as_uint(As[(ar + i * 16) * A_PITCH + ac]);
                af[i][1] = __float_as_uint(As[(ar + i * 16 + 8) * A_PITCH + ac]);
                af[i][2] = __float_as_uint(As[(ar + i * 16) * A_PITCH + ac + 4]);
                af[i][3] = __float_as_uint(As[(ar + i * 16 + 8) * A_PITCH + ac + 4]);
            }
            int br = ks * 8 + (lane & 3);
            int bc = wn + (lane >> 2);
            #pragma unroll
            for (int j = 0; j < 8; j++) {
                bf[j][0] = __float_as_uint(Bs[br * B_PITCH + bc + j * 8]);
                bf[j][1] = __float_as_uint(Bs[(br + 4) * B_PITCH + bc + j * 8]);
            }
            #pragma unroll
            for (int i = 0; i < 4; i++)
                #pragma unroll
                for (int j = 0; j < 8; j++)
                    mma8(acc[i][j], af[i], bf[j]);
        }
        __syncthreads();
        if (tid == 0 && s + STAGES - 1 < KC) issue(s + STAGES - 1);
        if (++slot == STAGES) { slot = 0; ph ^= 1; }
    }

    // ---- epilogue: write Y + fused column stats ----
    float* Yrow = g_Y + (size_t)(mt * 256) * NCOLS + h * 128;
    #pragma unroll
    for (int i = 0; i < 4; i++) {
        int r0 = wm + i * 16 + (lane >> 2);
        #pragma unroll
        for (int j = 0; j < 8; j++) {
            int cb = wn + j * 8 + (lane & 3) * 2;
            *(float2*)(Yrow + (size_t)r0 * NCOLS + cb) = make_float2(acc[i][j][0], acc[i][j][1]);
            *(float2*)(Yrow + (size_t)(r0 + 8) * NCOLS + cb) = make_float2(acc[i][j][2], acc[i][j][3]);
        }
    }

    #pragma unroll
    for (int j = 0; j < 8; j++) {
        #pragma unroll
        for (int e = 0; e < 2; e++) {
            float s = 0.f, q = 0.f;
            #pragma unroll
            for (int i = 0; i < 4; i++) {
                float v0 = acc[i][j][e], v1 = acc[i][j][e + 2];
                s += v0 + v1;
                q += v0 * v0 + v1 * v1;
            }
            #pragma unroll
            for (int m = 16; m >= 4; m >>= 1) {
                s += __shfl_xor_sync(0xffffffffu, s, m);
                q += __shfl_xor_sync(0xffffffffu, q, m);
            }
            if ((lane >> 2) == 0) {
                int col = h * 128 + wn + j * 8 + (lane & 3) * 2 + e;
                atomicAdd(&g_sum[col], s);
                atomicAdd(&g_sumsq[col], q);
            }
        }
    }
}

// ---- BN finalize + BN/ReLU + per-head 1x1 conv + concat ----
__global__ __launch_bounds__(256) void head_kernel(
    const float* __restrict__ gamma, const float* __restrict__ beta,
    const float* __restrict__ w0, const float* __restrict__ b0,
    const float* __restrict__ w1, const float* __restrict__ b1,
    const float* __restrict__ w2, const float* __restrict__ b2,
    const float* __restrict__ w3, const float* __restrict__ b3,
    const float* __restrict__ w4, const float* __restrict__ b4,
    float* __restrict__ out, int N) {
    __shared__ float Ys[64 * 129];
    __shared__ float sc[NCOLS], bi[NCOLS];
    int n0 = blockIdx.x * 64;
    int tid = threadIdx.x;

    for (int t = tid; t < NCOLS; t += 256) {
        float inv = 1.f / (float)N;
        float mean = g_sum[t] * inv;
        float var = g_sumsq[t] * inv - mean * mean;
        float s = gamma[t] * rsqrtf(var + EPS);
        sc[t] = s;
        bi[t] = beta[t] - mean * s;
    }
    __syncthreads();

    const float* W[H] = {w0, w1, w2, w3, w4};
    const float* B[H] = {b0, b1, b2, b3, b4};
    const int OC[H] = {3, 2, 1, 3, 2};
    const int OFF[H] = {0, 3, 5, 6, 9};

    #pragma unroll
    for (int h = 0; h < H; h++) {
        for (int i = tid; i < 64 * C; i += 256) {
            int r = i >> 7, c = i & 127;
            int n = n0 + r;
            float v = 0.f;
            if (n < N) {
                v = g_Y[(size_t)n * NCOLS + h * 128 + c];
                v = fmaxf(v * sc[h * 128 + c] + bi[h * 128 + c], 0.f);
            }
            Ys[r * 129 + c] = v;
        }
        __syncthreads();
        const int oc = OC[h];
        for (int o = tid; o < 64 * oc; o += 256) {
            int r = o / oc, jj = o - r * oc;
            int n = n0 + r;
            if (n < N) {
                float a = B[h][jj];
                const float* wp = W[h];
                #pragma unroll 8
                for (int c = 0; c < C; c++)
                    a += Ys[r * 129 + c] * wp[c * oc + jj];
                out[(size_t)n * 11 + OFF[h] + jj] = a;
            }
        }
        __syncthreads();
    }
}

extern "C" void kernel_launch(void* const* d_in, const int* in_sizes, int n_in,
                              void* d_out, int out_size) {
    const float* feats = (const float*)d_in[0];
    const int*   nbr   = (const int*)d_in[1];
    const float* W1    = (const float*)d_in[2];
    float* out = (float*)d_out;

    int N = in_sizes[0] / C;
    int MT = (N + 255) / 256;

    cudaFuncSetAttribute(gemm_kernel, cudaFuncAttributeMaxDynamicSharedMemorySize, GEMM_SMEM);

    int padrows = MT * 256 - N;
    int prep_total = WPREP_TOTAL + 2 * NCOLS + padrows * KC * A_PITCH;
    prep_kernel<<<(prep_total + 255) / 256, 256>>>(W1, N, MT);
    gather_kernel<<<(N * K2 + 7) / 8, 256>>>(feats, nbr, N);
    gemm_kernel<<<dim3(H, MT), 256, GEMM_SMEM>>>();
    head_kernel<<<(N + 63) / 64, 256>>>(
        (const float*)d_in[3], (const float*)d_in[4],
        (const float*)d_in[5], (const float*)d_in[6],
        (const float*)d_in[7], (const float*)d_in[8],
        (const float*)d_in[9], (const float*)d_in[10],
        (const float*)d_in[11], (const float*)d_in[12],
        (const float*)d_in[13], (const float*)d_in[14], out, N);
}

// round 5
// speedup vs baseline: 1.1128x; 1.0044x over previous
#include <cuda_runtime.h>
#include <cstdint>

#define C 128
#define K2 9
#define H 5
#define KDIM 1152
#define NCOLS 640
#define MT_MAX 157           // tiles of 256 rows, covers N<=40192
#define MPAD (MT_MAX * 256)
#define KC 36                // K chunks of 32
#define STAGES 4
#define EPS 1e-5f

// A tile image: 256 rows x 36 words (pitch 36, conflict-free LDS), 36864 B
#define A_PITCH 36
#define A_IMG_W (256 * A_PITCH)
#define A_IMG_B (A_IMG_W * 4)            // 36864
// B tile image: 32 rows x 136 words (pitch 136), 17408 B
#define B_PITCH 136
#define B_IMG_W (32 * B_PITCH)
#define B_IMG_B (B_IMG_W * 4)
#define GEMM_SMEM (STAGES * (A_IMG_B + B_IMG_B))   // 217088

// ---- device-global scratch (allocation-free) ----
__device__ float g_G[(size_t)MT_MAX * KC * A_IMG_W];   // im2col images (~208 MB)
__device__ float g_Wt[(size_t)H * KC * B_IMG_W];       // weight images (~3.1 MB)
__device__ float g_Y[(size_t)MPAD * NCOLS];            // pre-BN activations (~103 MB)
__device__ float g_sum[NCOLS];
__device__ float g_sumsq[NCOLS];

// ---- helpers ----
__device__ __forceinline__ float tf32r(float x) {
    unsigned u;
    asm("cvt.rna.tf32.f32 %0, %1;" : "=r"(u) : "f"(x));
    return __uint_as_float(u);
}
__device__ __forceinline__ uint32_t smem_u32(const void* p) {
    uint32_t a;
    asm("{ .reg .u64 t; cvta.to.shared.u64 t, %1; cvt.u32.u64 %0, t; }" : "=r"(a) : "l"(p));
    return a;
}
__device__ __forceinline__ void mma8(float* d, const unsigned* a, const unsigned* b) {
    asm volatile(
        "mma.sync.aligned.m16n8k8.row.col.f32.tf32.tf32.f32 "
        "{%0,%1,%2,%3}, {%4,%5,%6,%7}, {%8,%9}, {%0,%1,%2,%3};\n"
        : "+f"(d[0]), "+f"(d[1]), "+f"(d[2]), "+f"(d[3])
        : "r"(a[0]), "r"(a[1]), "r"(a[2]), "r"(a[3]),
          "r"(b[0]), "r"(b[1]));
}
__device__ __forceinline__ void bulk_g2s(uint32_t dst, const void* src, uint32_t bytes, uint32_t mbar) {
    asm volatile(
        "cp.async.bulk.shared::cluster.global.mbarrier::complete_tx::bytes [%0], [%1], %2, [%3];"
        :: "r"(dst), "l"(src), "r"(bytes), "r"(mbar) : "memory");
}
#define MBAR_INIT(a, n) asm volatile("mbarrier.init.shared.b64 [%0], %1;" :: "r"(a), "r"(n) : "memory")
#define MBAR_EXPECT(a, n) asm volatile("mbarrier.arrive.expect_tx.shared.b64 _, [%0], %1;" :: "r"(a), "r"(n) : "memory")

__device__ __forceinline__ void mbar_wait(uint32_t mbar, uint32_t parity) {
    asm volatile(
        "{\n\t.reg .pred P1;\n\t"
        "WAIT_LOOP_%=:\n\t"
        "mbarrier.try_wait.parity.acquire.cta.shared::cta.b64 P1, [%0], %1, 0x989680;\n\t"
        "@P1 bra.uni WAIT_DONE_%=;\n\t"
        "bra.uni WAIT_LOOP_%=;\n\t"
        "WAIT_DONE_%=:\n\t}"
        :: "r"(mbar), "r"(parity) : "memory");
}

// ---- prep: weight transpose/round + stats zero + A-image pad zero ----
#define WPREP_TOTAL (H * KDIM * C)
__global__ void prep_kernel(const float* __restrict__ W1, int N, int MT) {
    int gi = blockIdx.x * 256 + threadIdx.x;
    if (gi < WPREP_TOTAL) {
        int n = gi & 127;
        int k = (gi >> 7) % KDIM;
        int h = gi / (KDIM * C);
        int tap = k >> 7, cin = k & 127;
        float val = tf32r(W1[(((size_t)h * K2 + tap) * C + cin) * C + n]);
        g_Wt[((size_t)(h * KC + (k >> 5))) * B_IMG_W + (k & 31) * B_PITCH + n] = val;
        return;
    }
    int j = gi - WPREP_TOTAL;
    if (j < 2 * NCOLS) {
        if (j < NCOLS) g_sum[j] = 0.f; else g_sumsq[j - NCOLS] = 0.f;
        return;
    }
    int i = j - 2 * NCOLS;
    int padrows = MT * 256 - N;
    int total = padrows * KC * A_PITCH;
    if (i < total && padrows > 0) {
        int kc = i / (padrows * A_PITCH);
        int rem = i - kc * padrows * A_PITCH;
        int r = (N & 255) + rem / A_PITCH;
        int cw = rem % A_PITCH;
        g_G[(size_t)((MT - 1) * KC + kc) * A_IMG_W + r * A_PITCH + cw] = 0.f;
    }
}

// ---- gather: im2col rows into A tile images (tf32-rounded) ----
__global__ __launch_bounds__(256) void gather_kernel(const float* __restrict__ feats,
                                                     const int* __restrict__ nbr, int N) {
    int w = blockIdx.x * 8 + (threadIdx.x >> 5);
    int lane = threadIdx.x & 31;
    if (w >= N * K2) return;
    int n = w / K2, tap = w - n * K2;
    int idx = __ldg(&nbr[w]);
    float4 v = *(const float4*)(feats + (size_t)idx * C + lane * 4);
    v.x = tf32r(v.x); v.y = tf32r(v.y); v.z = tf32r(v.z); v.w = tf32r(v.w);
    size_t img = (size_t)((n >> 8) * KC + tap * 4 + (lane >> 3)) * A_IMG_W;
    *(float4*)(g_G + img + (n & 255) * A_PITCH + (lane & 7) * 4) = v;
}

// ---- GEMM: 256x128 CTA tile, 64x64 warp tiles, bulk-async pipeline, fused stats ----
__global__ __launch_bounds__(256, 1) void gemm_kernel() {
    extern __shared__ float sm[];
    __shared__ __align__(8) unsigned long long mbars[STAGES];

    const int tid = threadIdx.x;
    const int h = blockIdx.x;
    const int mt = blockIdx.y;
    const int warp = tid >> 5, lane = tid & 31;
    const int wm = (warp >> 1) * 64;   // 0,64,128,192
    const int wn = (warp & 1) * 64;    // 0,64

    uint32_t mb = smem_u32(mbars);
    uint32_t smb = smem_u32(sm);
    if (tid == 0) {
        #pragma unroll
        for (int i = 0; i < STAGES; i++) MBAR_INIT(mb + i * 8, 1);
    }
    __syncthreads();

    const float* Gt = g_G + (size_t)mt * KC * A_IMG_W;
    const float* Bt = g_Wt + (size_t)h * KC * B_IMG_W;

    auto issue = [&](int s) {
        int slot = s % STAGES;
        uint32_t full = mb + slot * 8;
        MBAR_EXPECT(full, A_IMG_B + B_IMG_B);
        bulk_g2s(smb + slot * A_IMG_B, Gt + (size_t)s * A_IMG_W, A_IMG_B, full);
        bulk_g2s(smb + STAGES * A_IMG_B + slot * B_IMG_B, Bt + (size_t)s * B_IMG_W, B_IMG_B, full);
    };

    if (tid == 0) {
        #pragma unroll
        for (int s = 0; s < STAGES - 1; s++) issue(s);
    }

    float acc[4][8][4];
    #pragma unroll
    for (int i = 0; i < 4; i++)
        #pragma unroll
        for (int j = 0; j < 8; j++)
            #pragma unroll
            for (int e = 0; e < 4; e++) acc[i][j][e] = 0.f;

    int slot = 0, ph = 0;
    for (int s = 0; s < KC; s++) {
        mbar_wait(mb + slot * 8, ph);
        const float* As = sm + slot * (A_IMG_B / 4);
        const float* Bs = sm + STAGES * (A_IMG_B / 4) + slot * (B_IMG_B / 4);

        #pragma unroll
        for (int ks = 0; ks < 4; ks++) {
            unsigned af[4][4], bf[8][2];
            int ac = ks * 8 + (lane & 3);
            int ar = wm + (lane >> 2);
            #pragma unroll
            for (int i = 0; i < 4; i++) {
                af[i][0] = __float_as_uint(As[(ar + i * 16) * A_PITCH + ac]);
                af[i][1] = __float_as_uint(As[(ar + i * 16 + 8) * A_PITCH + ac]);
                af[i][2] = __float_as_uint(As[(ar + i * 16) * A_PITCH + ac + 4]);
                af[i][3] = __float_as_uint(As[(ar + i * 16 + 8) * A_PITCH + ac + 4]);
            }
            int br = ks * 8 + (lane & 3);
            int bc = wn + (lane >> 2);
            #pragma unroll
            for (int j = 0; j < 8; j++) {
                bf[j][0] = __float_as_uint(Bs[br * B_PITCH + bc + j * 8]);
                bf[j][1] = __float_as_uint(Bs[(br + 4) * B_PITCH + bc + j * 8]);
            }
            #pragma unroll
            for (int i = 0; i < 4; i++)
                #pragma unroll
                for (int j = 0; j < 8; j++)
                    mma8(acc[i][j], af[i], bf[j]);
        }
        __syncthreads();
        if (tid == 0 && s + STAGES - 1 < KC) issue(s + STAGES - 1);
        if (++slot == STAGES) { slot = 0; ph ^= 1; }
    }

    // ---- epilogue: write Y + fused column stats ----
    float* Yrow = g_Y + (size_t)(mt * 256) * NCOLS + h * 128;
    #pragma unroll
    for (int i = 0; i < 4; i++) {
        int r0 = wm + i * 16 + (lane >> 2);
        #pragma unroll
        for (int j = 0; j < 8; j++) {
            int cb = wn + j * 8 + (lane & 3) * 2;
            *(float2*)(Yrow + (size_t)r0 * NCOLS + cb) = make_float2(acc[i][j][0], acc[i][j][1]);
            *(float2*)(Yrow + (size_t)(r0 + 8) * NCOLS + cb) = make_float2(acc[i][j][2], acc[i][j][3]);
        }
    }

    #pragma unroll
    for (int j = 0; j < 8; j++) {
        #pragma unroll
        for (int e = 0; e < 2; e++) {
            float s = 0.f, q = 0.f;
            #pragma unroll
            for (int i = 0; i < 4; i++) {
                float v0 = acc[i][j][e], v1 = acc[i][j][e + 2];
                s += v0 + v1;
                q += v0 * v0 + v1 * v1;
            }
            #pragma unroll
            for (int m = 16; m >= 4; m >>= 1) {
                s += __shfl_xor_sync(0xffffffffu, s, m);
                q += __shfl_xor_sync(0xffffffffu, q, m);
            }
            if ((lane >> 2) == 0) {
                int col = h * 128 + wn + j * 8 + (lane & 3) * 2 + e;
                atomicAdd(&g_sum[col], s);
                atomicAdd(&g_sumsq[col], q);
            }
        }
    }
}

// ---- BN finalize + BN/ReLU + per-head 1x1 conv + concat ----
__global__ __launch_bounds__(256) void head_kernel(
    const float* __restrict__ gamma, const float* __restrict__ beta,
    const float* __restrict__ w0, const float* __restrict__ b0,
    const float* __restrict__ w1, const float* __restrict__ b1,
    const float* __restrict__ w2, const float* __restrict__ b2,
    const float* __restrict__ w3, const float* __restrict__ b3,
    const float* __restrict__ w4, const float* __restrict__ b4,
    float* __restrict__ out, int N) {
    __shared__ float Ys[64 * 129];
    __shared__ float sc[NCOLS], bi[NCOLS];
    int n0 = blockIdx.x * 64;
    int tid = threadIdx.x;

    for (int t = tid; t < NCOLS; t += 256) {
        float inv = 1.f / (float)N;
        float mean = g_sum[t] * inv;
        float var = g_sumsq[t] * inv - mean * mean;
        float s = gamma[t] * rsqrtf(var + EPS);
        sc[t] = s;
        bi[t] = beta[t] - mean * s;
    }
    __syncthreads();

    const float* W[H] = {w0, w1, w2, w3, w4};
    const float* B[H] = {b0, b1, b2, b3, b4};
    const int OC[H] = {3, 2, 1, 3, 2};
    const int OFF[H] = {0, 3, 5, 6, 9};

    #pragma unroll
    for (int h = 0; h < H; h++) {
        for (int i = tid; i < 64 * C; i += 256) {
            int r = i >> 7, c = i & 127;
            int n = n0 + r;
            float v = 0.f;
            if (n < N) {
                v = g_Y[(size_t)n * NCOLS + h * 128 + c];
                v = fmaxf(v * sc[h * 128 + c] + bi[h * 128 + c], 0.f);
            }
            Ys[r * 129 + c] = v;
        }
        __syncthreads();
        const int oc = OC[h];
        for (int o = tid; o < 64 * oc; o += 256) {
            int r = o / oc, jj = o - r * oc;
            int n = n0 + r;
            if (n < N) {
                float a = B[h][jj];
                const float* wp = W[h];
                #pragma unroll 8
                for (int c = 0; c < C; c++)
                    a += Ys[r * 129 + c] * wp[c * oc + jj];
                out[(size_t)n * 11 + OFF[h] + jj] = a;
            }
        }
        __syncthreads();
    }
}

extern "C" void kernel_launch(void* const* d_in, const int* in_sizes, int n_in,
                              void* d_out, int out_size) {
    const float* feats = (const float*)d_in[0];
    const int*   nbr   = (const int*)d_in[1];
    const float* W1    = (const float*)d_in[2];
    float* out = (float*)d_out;

    int N = in_sizes[0] / C;
    int MT = (N + 255) / 256;

    cudaFuncSetAttribute(gemm_kernel, cudaFuncAttributeMaxDynamicSharedMemorySize, GEMM_SMEM);

    int padrows = MT * 256 - N;
    int prep_total = WPREP_TOTAL + 2 * NCOLS + padrows * KC * A_PITCH;
    prep_kernel<<<(prep_total + 255) / 256, 256>>>(W1, N, MT);
    gather_kernel<<<(N * K2 + 7) / 8, 256>>>(feats, nbr, N);
    gemm_kernel<<<dim3(H, MT), 256, GEMM_SMEM>>>();
    head_kernel<<<(N + 63) / 64, 256>>>(
        (const float*)d_in[3], (const float*)d_in[4],
        (const float*)d_in[5], (const float*)d_in[6],
        (const float*)d_in[7], (const float*)d_in[8],
        (const float*)d_in[9], (const float*)d_in[10],
        (const float*)d_in[11], (const float*)d_in[12],
        (const float*)d_in[13], (const float*)d_in[14], out, N);
}

// round 8
// speedup vs baseline: 1.2111x; 1.0883x over previous
#include <cuda_runtime.h>
#include <cstdint>

#define C 128
#define K2 9
#define H 5
#define KDIM 1152
#define NCOLS 640
#define MT_MAX 157           // tiles of 256 rows, covers N<=40192
#define MPAD (MT_MAX * 256)
#define KC 36                // K chunks of 32
#define STAGES 4
#define EPS 1e-5f

// A tile image: 256 rows x 36 words (pitch 36, conflict-free LDS), 36864 B
#define A_PITCH 36
#define A_IMG_W (256 * A_PITCH)
#define A_IMG_B (A_IMG_W * 4)
// B tile image: 32 rows x 136 words (pitch 136), 17408 B
#define B_PITCH 136
#define B_IMG_W (32 * B_PITCH)
#define B_IMG_B (B_IMG_W * 4)
#define GEMM_SMEM (STAGES * (A_IMG_B + B_IMG_B))   // 217088

// ---- device-global scratch (allocation-free) ----
__device__ float g_G[(size_t)MT_MAX * KC * A_IMG_W];   // im2col images (~208 MB)
__device__ float g_Wt[(size_t)H * KC * B_IMG_W];       // weight images (~3.1 MB)
__device__ float g_Y[(size_t)MPAD * NCOLS];            // pre-BN activations (~103 MB)
__device__ float g_sum[NCOLS];
__device__ float g_sumsq[NCOLS];

// ---- helpers ----
__device__ __forceinline__ float tf32r(float x) {
    unsigned u;
    asm("cvt.rna.tf32.f32 %0, %1;" : "=r"(u) : "f"(x));
    return __uint_as_float(u);
}
__device__ __forceinline__ uint32_t smem_u32(const void* p) {
    uint32_t a;
    asm("{ .reg .u64 t; cvta.to.shared.u64 t, %1; cvt.u32.u64 %0, t; }" : "=r"(a) : "l"(p));
    return a;
}
__device__ __forceinline__ void mma8(float* d, const unsigned* a, const unsigned* b) {
    asm volatile(
        "mma.sync.aligned.m16n8k8.row.col.f32.tf32.tf32.f32 "
        "{%0,%1,%2,%3}, {%4,%5,%6,%7}, {%8,%9}, {%0,%1,%2,%3};\n"
        : "+f"(d[0]), "+f"(d[1]), "+f"(d[2]), "+f"(d[3])
        : "r"(a[0]), "r"(a[1]), "r"(a[2]), "r"(a[3]),
          "r"(b[0]), "r"(b[1]));
}
__device__ __forceinline__ void bulk_g2s(uint32_t dst, const void* src, uint32_t bytes, uint32_t mbar) {
    asm volatile(
        "cp.async.bulk.shared::cluster.global.mbarrier::complete_tx::bytes [%0], [%1], %2, [%3];"
        :: "r"(dst), "l"(src), "r"(bytes), "r"(mbar) : "memory");
}
#define MBAR_INIT(a, n) asm volatile("mbarrier.init.shared.b64 [%0], %1;" :: "r"(a), "r"(n) : "memory")
#define MBAR_EXPECT(a, n) asm volatile("mbarrier.arrive.expect_tx.shared.b64 _, [%0], %1;" :: "r"(a), "r"(n) : "memory")

__device__ __forceinline__ void mbar_wait(uint32_t mbar, uint32_t parity) {
    asm volatile(
        "{\n\t.reg .pred P1;\n\t"
        "WAIT_LOOP_%=:\n\t"
        "mbarrier.try_wait.parity.acquire.cta.shared::cta.b64 P1, [%0], %1, 0x989680;\n\t"
        "@P1 bra.uni WAIT_DONE_%=;\n\t"
        "bra.uni WAIT_LOOP_%=;\n\t"
        "WAIT_DONE_%=:\n\t}"
        :: "r"(mbar), "r"(parity) : "memory");
}
__device__ __forceinline__ void bar_arrive_1_288() {
    asm volatile("bar.arrive 1, 288;" ::: "memory");
}
__device__ __forceinline__ void bar_sync_1_288() {
    asm volatile("bar.sync 1, 288;" ::: "memory");
}
__device__ __forceinline__ uint32_t elect1() {
    uint32_t p;
    asm volatile("{\n\t.reg .pred p;\n\telect.sync _|p, 0xFFFFFFFF;\n\tselp.b32 %0, 1, 0, p;\n\t}"
                 : "=r"(p));
    return p;
}

// ---- prep: weight transpose/round + stats zero + A-image pad zero ----
#define WPREP_TOTAL (H * KDIM * C)
__global__ void prep_kernel(const float* __restrict__ W1, int N, int MT) {
    int gi = blockIdx.x * 256 + threadIdx.x;
    if (gi < WPREP_TOTAL) {
        int n = gi & 127;
        int k = (gi >> 7) % KDIM;
        int h = gi / (KDIM * C);
        int tap = k >> 7, cin = k & 127;
        float val = tf32r(W1[(((size_t)h * K2 + tap) * C + cin) * C + n]);
        g_Wt[((size_t)(h * KC + (k >> 5))) * B_IMG_W + (k & 31) * B_PITCH + n] = val;
        return;
    }
    int j = gi - WPREP_TOTAL;
    if (j < 2 * NCOLS) {
        if (j < NCOLS) g_sum[j] = 0.f; else g_sumsq[j - NCOLS] = 0.f;
        return;
    }
    int i = j - 2 * NCOLS;
    int padrows = MT * 256 - N;
    int total = padrows * KC * A_PITCH;
    if (i < total && padrows > 0) {
        int kc = i / (padrows * A_PITCH);
        int rem = i - kc * padrows * A_PITCH;
        int r = (N & 255) + rem / A_PITCH;
        int cw = rem % A_PITCH;
        g_G[(size_t)((MT - 1) * KC + kc) * A_IMG_W + r * A_PITCH + cw] = 0.f;
    }
}

// ---- gather: im2col rows into A tile images (tf32-rounded) ----
__global__ __launch_bounds__(256) void gather_kernel(const float* __restrict__ feats,
                                                     const int* __restrict__ nbr, int N) {
    int w = blockIdx.x * 8 + (threadIdx.x >> 5);
    int lane = threadIdx.x & 31;
    if (w >= N * K2) return;
    int n = w / K2, tap = w - n * K2;
    int idx = __ldg(&nbr[w]);
    float4 v = *(const float4*)(feats + (size_t)idx * C + lane * 4);
    v.x = tf32r(v.x); v.y = tf32r(v.y); v.z = tf32r(v.z); v.w = tf32r(v.w);
    size_t img = (size_t)((n >> 8) * KC + tap * 4 + (lane >> 3)) * A_IMG_W;
    *(float4*)(g_G + img + (n & 255) * A_PITCH + (lane & 7) * 4) = v;
}

// ---- GEMM: 256x128 CTA tile, 64x64 warp tiles, producer warp + named barriers ----
__global__ __launch_bounds__(288, 1) void gemm_kernel() {
    extern __shared__ float sm[];
    __shared__ __align__(8) unsigned long long mbars[STAGES];

    const int tid = threadIdx.x;
    const int h = blockIdx.x;
    const int mt = blockIdx.y;
    const int warp = tid >> 5, lane = tid & 31;

    uint32_t mb = smem_u32(mbars);
    uint32_t smb = smem_u32(sm);
    if (tid == 0) {
        #pragma unroll
        for (int i = 0; i < STAGES; i++) MBAR_INIT(mb + i * 8, 1);
    }
    __syncthreads();

    const float* Gt = g_G + (size_t)mt * KC * A_IMG_W;
    const float* Bt = g_Wt + (size_t)h * KC * B_IMG_W;

    if (warp == 8) {
        // ---- producer warp ----
        uint32_t e = elect1();
        if (e) {
            #pragma unroll
            for (int s = 0; s < STAGES - 1; s++) {
                int slot = s;
                uint32_t full = mb + slot * 8;
                MBAR_EXPECT(full, A_IMG_B + B_IMG_B);
                bulk_g2s(smb + slot * A_IMG_B, Gt + (size_t)s * A_IMG_W, A_IMG_B, full);
                bulk_g2s(smb + STAGES * A_IMG_B + slot * B_IMG_B, Bt + (size_t)s * B_IMG_W, B_IMG_B, full);
            }
        }
        for (int s = STAGES - 1; s < KC; s++) {
            bar_sync_1_288();          // wait for math warps to finish stage s-(STAGES-1)
            if (e) {
                int slot = s % STAGES;
                uint32_t full = mb + slot * 8;
                MBAR_EXPECT(full, A_IMG_B + B_IMG_B);
                bulk_g2s(smb + slot * A_IMG_B, Gt + (size_t)s * A_IMG_W, A_IMG_B, full);
                bulk_g2s(smb + STAGES * A_IMG_B + slot * B_IMG_B, Bt + (size_t)s * B_IMG_W, B_IMG_B, full);
            }
        }
        return;
    }

    // ---- math warps (0..7) ----
    const int wm = (warp >> 1) * 64;   // 0,64,128,192
    const int wn = (warp & 1) * 64;    // 0,64

    float acc[4][8][4];
    #pragma unroll
    for (int i = 0; i < 4; i++)
        #pragma unroll
        for (int j = 0; j < 8; j++)
            #pragma unroll
            for (int e = 0; e < 4; e++) acc[i][j][e] = 0.f;

    int slot = 0, ph = 0;
    for (int s = 0; s < KC; s++) {
        mbar_wait(mb + slot * 8, ph);
        const float* As = sm + slot * (A_IMG_B / 4);
        const float* Bs = sm + STAGES * (A_IMG_B / 4) + slot * (B_IMG_B / 4);

        #pragma unroll
        for (int ks = 0; ks < 4; ks++) {
            unsigned af[4][4], bf[8][2];
            int ac = ks * 8 + (lane & 3);
            int ar = wm + (lane >> 2);
            #pragma unroll
            for (int i = 0; i < 4; i++) {
                af[i][0] = __float_as_uint(As[(ar + i * 16) * A_PITCH + ac]);
                af[i][1] = __float_as_uint(As[(ar + i * 16 + 8) * A_PITCH + ac]);
                af[i][2] = __float_as_uint(As[(ar + i * 16) * A_PITCH + ac + 4]);
                af[i][3] = __float_as_uint(As[(ar + i * 16 + 8) * A_PITCH + ac + 4]);
            }
            int br = ks * 8 + (lane & 3);
            int bc = wn + (lane >> 2);
            #pragma unroll
            for (int j = 0; j < 8; j++) {
                bf[j][0] = __float_as_uint(Bs[br * B_PITCH + bc + j * 8]);
                bf[j][1] = __float_as_uint(Bs[(br + 4) * B_PITCH + bc + j * 8]);
            }
            #pragma unroll
            for (int i = 0; i < 4; i++)
                #pragma unroll
                for (int j = 0; j < 8; j++)
                    mma8(acc[i][j], af[i], bf[j]);
        }
        bar_arrive_1_288();            // signal stage consumed (non-blocking)
        if (++slot == STAGES) { slot = 0; ph ^= 1; }
    }

    // ---- epilogue: write Y + fused column stats ----
    float* Yrow = g_Y + (size_t)(mt * 256) * NCOLS + h * 128;
    #pragma unroll
    for (int i = 0; i < 4; i++) {
        int r0 = wm + i * 16 + (lane >> 2);
        #pragma unroll
        for (int j = 0; j < 8; j++) {
            int cb = wn + j * 8 + (lane & 3) * 2;
            *(float2*)(Yrow + (size_t)r0 * NCOLS + cb) = make_float2(acc[i][j][0], acc[i][j][1]);
            *(float2*)(Yrow + (size_t)(r0 + 8) * NCOLS + cb) = make_float2(acc[i][j][2], acc[i][j][3]);
        }
    }

    #pragma unroll
    for (int j = 0; j < 8; j++) {
        #pragma unroll
        for (int e = 0; e < 2; e++) {
            float s = 0.f, q = 0.f;
            #pragma unroll
            for (int i = 0; i < 4; i++) {
                float v0 = acc[i][j][e], v1 = acc[i][j][e + 2];
                s += v0 + v1;
                q += v0 * v0 + v1 * v1;
            }
            #pragma unroll
            for (int m = 16; m >= 4; m >>= 1) {
                s += __shfl_xor_sync(0xffffffffu, s, m);
                q += __shfl_xor_sync(0xffffffffu, q, m);
            }
            if ((lane >> 2) == 0) {
                int col = h * 128 + wn + j * 8 + (lane & 3) * 2 + e;
                atomicAdd(&g_sum[col], s);
                atomicAdd(&g_sumsq[col], q);
            }
        }
    }
}

// ---- head: warp-per-row, BN finalize + BN/ReLU + 1x1 convs + concat ----
#define ROWS_PER_BLOCK 64
__global__ __launch_bounds__(256) void head_kernel(
    const float* __restrict__ gamma, const float* __restrict__ beta,
    const float* __restrict__ w0, const float* __restrict__ b0,
    const float* __restrict__ w1, const float* __restrict__ b1,
    const float* __restrict__ w2, const float* __restrict__ b2,
    const float* __restrict__ w3, const float* __restrict__ b3,
    const float* __restrict__ w4, const float* __restrict__ b4,
    float* __restrict__ out, int N) {
    __shared__ float scm[NCOLS], bim[NCOLS];
    __shared__ float wsm[NCOLS * 5];     // pitch 5 per column (max oc=3, pad)
    __shared__ float bsm[16];
    const int tid = threadIdx.x;
    const int warp = tid >> 5, lane = tid & 31;
    const int n0 = blockIdx.x * ROWS_PER_BLOCK;

    const int OC0 = 3, OC1 = 2, OC2 = 1, OC3 = 3, OC4 = 2;

    for (int t = tid; t < NCOLS; t += 256) {
        float inv = 1.f / (float)N;
        float mean = g_sum[t] * inv;
        float var = g_sumsq[t] * inv - mean * mean;
        float s = gamma[t] * rsqrtf(var + EPS);
        scm[t] = s;
        bim[t] = beta[t] - mean * s;
        int h = t >> 7, c = t & 127;
        const float* wp; int oc;
        switch (h) {
            case 0: wp = w0; oc = OC0; break;
            case 1: wp = w1; oc = OC1; break;
            case 2: wp = w2; oc = OC2; break;
            case 3: wp = w3; oc = OC3; break;
            default: wp = w4; oc = OC4; break;
        }
        #pragma unroll 3
        for (int o = 0; o < 3; o++)
            wsm[t * 5 + o] = (o < oc) ? wp[c * oc + o] : 0.f;
    }
    if (tid < 11) {
        float bv;
        if (tid < 3) bv = b0[tid];
        else if (tid < 5) bv = b1[tid - 3];
        else if (tid < 6) bv = b2[tid - 5];
        else if (tid < 9) bv = b3[tid - 6];
        else bv = b4[tid - 9];
        bsm[tid] = bv;
    }
    __syncthreads();

    for (int r = warp; r < ROWS_PER_BLOCK; r += 8) {
        int n = n0 + r;
        if (n >= N) break;
        const float* Yn = g_Y + (size_t)n * NCOLS;
        float acc[11];
        #pragma unroll
        for (int o = 0; o < 11; o++) acc[o] = 0.f;

        #define HEAD_ROUND(hh, OCC, OFFS)                                              \
        {                                                                              \
            int cb = hh * 128 + lane * 4;                                              \
            float4 v = *(const float4*)(Yn + cb);                                      \
            float4 s4 = *(const float4*)(scm + cb);                                    \
            float4 b4v = *(const float4*)(bim + cb);                                   \
            float vv[4];                                                               \
            vv[0] = fmaxf(v.x * s4.x + b4v.x, 0.f);                                    \
            vv[1] = fmaxf(v.y * s4.y + b4v.y, 0.f);                                    \
            vv[2] = fmaxf(v.z * s4.z + b4v.z, 0.f);                                    \
            vv[3] = fmaxf(v.w * s4.w + b4v.w, 0.f);                                    \
            _Pragma("unroll")                                                          \
            for (int j = 0; j < 4; j++) {                                              \
                const float* wrow = wsm + (size_t)(cb + j) * 5;                        \
                _Pragma("unroll")                                                      \
                for (int o = 0; o < OCC; o++)                                          \
                    acc[OFFS + o] += vv[j] * wrow[o];                                  \
            }                                                                          \
        }
        HEAD_ROUND(0, 3, 0)
        HEAD_ROUND(1, 2, 3)
        HEAD_ROUND(2, 1, 5)
        HEAD_ROUND(3, 3, 6)
        HEAD_ROUND(4, 2, 9)
        #undef HEAD_ROUND

        #pragma unroll
        for (int o = 0; o < 11; o++) {
            #pragma unroll
            for (int m = 16; m >= 1; m >>= 1)
                acc[o] += __shfl_xor_sync(0xffffffffu, acc[o], m);
        }
        if (lane < 11) {
            float val = acc[0];
            #pragma unroll
            for (int o = 1; o < 11; o++)
                if (lane == o) val = acc[o];
            out[(size_t)n * 11 + lane] = val + bsm[lane];
        }
    }
}

extern "C" void kernel_launch(void* const* d_in, const int* in_sizes, int n_in,
                              void* d_out, int out_size) {
    const float* feats = (const float*)d_in[0];
    const int*   nbr   = (const int*)d_in[1];
    const float* W1    = (const float*)d_in[2];
    float* out = (float*)d_out;

    int N = in_sizes[0] / C;
    int MT = (N + 255) / 256;

    cudaFuncSetAttribute(gemm_kernel, cudaFuncAttributeMaxDynamicSharedMemorySize, GEMM_SMEM);

    int padrows = MT * 256 - N;
    int prep_total = WPREP_TOTAL + 2 * NCOLS + padrows * KC * A_PITCH;
    prep_kernel<<<(prep_total + 255) / 256, 256>>>(W1, N, MT);
    gather_kernel<<<(N * K2 + 7) / 8, 256>>>(feats, nbr, N);
    gemm_kernel<<<dim3(H, MT), 288, GEMM_SMEM>>>();
    head_kernel<<<(N + ROWS_PER_BLOCK - 1) / ROWS_PER_BLOCK, 256>>>(
        (const float*)d_in[3], (const float*)d_in[4],
        (const float*)d_in[5], (const float*)d_in[6],
        (const float*)d_in[7], (const float*)d_in[8],
        (const float*)d_in[9], (const float*)d_in[10],
        (const float*)d_in[11], (const float*)d_in[12],
        (const float*)d_in[13], (const float*)d_in[14], out, N);
}

// round 9
// speedup vs baseline: 1.8139x; 1.4977x over previous
#include <cuda_runtime.h>
#include <cuda_fp16.h>
#include <cstdint>

#define C 128
#define K2 9
#define H 5
#define KDIM 1152
#define NCOLS 640
#define MT_MAX 157           // tiles of 256 rows, covers N<=40192
#define MPAD (MT_MAX * 256)
#define KC 36                // K chunks of 32 halfs
#define STAGES 6
#define EPS 1e-5f

// A chunk: 256 rows x 16 words (32 halfs) + 4 pad words -> pitch 20 (conflict-free)
#define A_PITCH_W 20
#define A_CHUNK_W (256 * A_PITCH_W)   // 5120 words
#define A_CHUNK_B (A_CHUNK_W * 4)     // 20480 B
// B chunk: 128 rows(n) x 16 words(k) + 4 pad -> pitch 20
#define B_PITCH_W 20
#define B_CHUNK_W (128 * B_PITCH_W)   // 2560 words
#define B_CHUNK_B (B_CHUNK_W * 4)     // 10240 B
#define GEMM_SMEM (STAGES * (A_CHUNK_B + B_CHUNK_B))   // 184320

// ---- device-global scratch (allocation-free) ----
__device__ uint32_t g_G[(size_t)MT_MAX * KC * A_CHUNK_W];   // fp16 im2col images (~116 MB)
__device__ uint32_t g_Wt[(size_t)H * KC * B_CHUNK_W];       // fp16 weight images (~1.8 MB)
__device__ float g_Y[(size_t)MPAD * NCOLS];                 // pre-BN activations (~103 MB)
__device__ float g_sum[NCOLS];
__device__ float g_sumsq[NCOLS];

// ---- helpers ----
__device__ __forceinline__ uint32_t pack2(float a, float b) {
    __half2 h = __floats2half2_rn(a, b);
    return *reinterpret_cast<uint32_t*>(&h);
}
__device__ __forceinline__ uint32_t smem_u32(const void* p) {
    uint32_t a;
    asm("{ .reg .u64 t; cvta.to.shared.u64 t, %1; cvt.u32.u64 %0, t; }" : "=r"(a) : "l"(p));
    return a;
}
__device__ __forceinline__ void mma16(float* d, const unsigned* a, const unsigned* b) {
    asm volatile(
        "mma.sync.aligned.m16n8k16.row.col.f32.f16.f16.f32 "
        "{%0,%1,%2,%3}, {%4,%5,%6,%7}, {%8,%9}, {%0,%1,%2,%3};\n"
        : "+f"(d[0]), "+f"(d[1]), "+f"(d[2]), "+f"(d[3])
        : "r"(a[0]), "r"(a[1]), "r"(a[2]), "r"(a[3]),
          "r"(b[0]), "r"(b[1]));
}
__device__ __forceinline__ void bulk_g2s(uint32_t dst, const void* src, uint32_t bytes, uint32_t mbar) {
    asm volatile(
        "cp.async.bulk.shared::cluster.global.mbarrier::complete_tx::bytes [%0], [%1], %2, [%3];"
        :: "r"(dst), "l"(src), "r"(bytes), "r"(mbar) : "memory");
}
#define MBAR_INIT(a, n) asm volatile("mbarrier.init.shared.b64 [%0], %1;" :: "r"(a), "r"(n) : "memory")
#define MBAR_EXPECT(a, n) asm volatile("mbarrier.arrive.expect_tx.shared.b64 _, [%0], %1;" :: "r"(a), "r"(n) : "memory")

__device__ __forceinline__ void mbar_wait(uint32_t mbar, uint32_t parity) {
    asm volatile(
        "{\n\t.reg .pred P1;\n\t"
        "WAIT_LOOP_%=:\n\t"
        "mbarrier.try_wait.parity.acquire.cta.shared::cta.b64 P1, [%0], %1, 0x989680;\n\t"
        "@P1 bra.uni WAIT_DONE_%=;\n\t"
        "bra.uni WAIT_LOOP_%=;\n\t"
        "WAIT_DONE_%=:\n\t}"
        :: "r"(mbar), "r"(parity) : "memory");
}
__device__ __forceinline__ void bar_arrive_1_288() {
    asm volatile("bar.arrive 1, 288;" ::: "memory");
}
__device__ __forceinline__ void bar_sync_1_288() {
    asm volatile("bar.sync 1, 288;" ::: "memory");
}
__device__ __forceinline__ uint32_t elect1() {
    uint32_t p;
    asm volatile("{\n\t.reg .pred p;\n\telect.sync _|p, 0xFFFFFFFF;\n\tselp.b32 %0, 1, 0, p;\n\t}"
                 : "=r"(p));
    return p;
}

// ---- prep: weight pack (fp16 k-pairs, n-major) + stats zero + A-image pad zero ----
#define WPREP_TOTAL (H * 576 * 128)     // one thread per (h, k-pair, n)
__global__ void prep_kernel(const float* __restrict__ W1, int N, int MT) {
    int gi = blockIdx.x * 256 + threadIdx.x;
    if (gi < WPREP_TOTAL) {
        int n = gi & 127;
        int kw = (gi >> 7) % 576;
        int h = gi / (576 * 128);
        int tap = kw >> 6;
        int rem = kw & 63;
        int cin0 = rem * 2;
        const float* p = W1 + (((size_t)h * K2 + tap) * C + cin0) * C + n;
        uint32_t u = pack2(p[0], p[C]);
        int kc = tap * 4 + (rem >> 4);
        int wc = rem & 15;
        g_Wt[((size_t)(h * KC + kc) * 128 + n) * B_PITCH_W + wc] = u;
        return;
    }
    int j = gi - WPREP_TOTAL;
    if (j < 2 * NCOLS) {
        if (j < NCOLS) g_sum[j] = 0.f; else g_sumsq[j - NCOLS] = 0.f;
        return;
    }
    int i = j - 2 * NCOLS;
    int padrows = MT * 256 - N;
    int total = padrows * KC * A_PITCH_W;
    if (i < total && padrows > 0) {
        int kc = i / (padrows * A_PITCH_W);
        int rem = i - kc * padrows * A_PITCH_W;
        int r = (N & 255) + rem / A_PITCH_W;
        int cw = rem % A_PITCH_W;
        g_G[(size_t)((MT - 1) * KC + kc) * A_CHUNK_W + r * A_PITCH_W + cw] = 0u;
    }
}

// ---- gather: im2col rows into fp16 A images ----
__global__ __launch_bounds__(256) void gather_kernel(const float* __restrict__ feats,
                                                     const int* __restrict__ nbr, int N) {
    int w = blockIdx.x * 8 + (threadIdx.x >> 5);
    int lane = threadIdx.x & 31;
    if (w >= N * K2) return;
    int n = w / K2, tap = w - n * K2;
    int idx = __ldg(&nbr[w]);
    float4 v = *(const float4*)(feats + (size_t)idx * C + lane * 4);
    uint2 u = make_uint2(pack2(v.x, v.y), pack2(v.z, v.w));
    int kc = tap * 4 + (lane >> 3);
    size_t addr = ((size_t)((n >> 8) * KC + kc) * 256 + (n & 255)) * A_PITCH_W + (lane & 7) * 2;
    *(uint2*)(g_G + addr) = u;
}

// ---- GEMM: 256x128 CTA tile, fp16 mma.sync, producer warp + named barriers ----
__global__ __launch_bounds__(288, 1) void gemm_kernel() {
    extern __shared__ uint32_t smw[];
    __shared__ __align__(8) unsigned long long mbars[STAGES];

    const int tid = threadIdx.x;
    const int h = blockIdx.x;
    const int mt = blockIdx.y;
    const int warp = tid >> 5, lane = tid & 31;

    uint32_t mb = smem_u32(mbars);
    uint32_t smb = smem_u32(smw);
    if (tid == 0) {
        #pragma unroll
        for (int i = 0; i < STAGES; i++) MBAR_INIT(mb + i * 8, 1);
    }
    __syncthreads();

    const uint32_t* Gt = g_G + (size_t)mt * KC * A_CHUNK_W;
    const uint32_t* Bt = g_Wt + (size_t)h * KC * B_CHUNK_W;

    if (warp == 8) {
        // ---- producer warp ----
        uint32_t e = elect1();
        if (e) {
            #pragma unroll
            for (int s = 0; s < STAGES - 1; s++) {
                uint32_t full = mb + s * 8;
                MBAR_EXPECT(full, A_CHUNK_B + B_CHUNK_B);
                bulk_g2s(smb + s * A_CHUNK_B, Gt + (size_t)s * A_CHUNK_W, A_CHUNK_B, full);
                bulk_g2s(smb + STAGES * A_CHUNK_B + s * B_CHUNK_B, Bt + (size_t)s * B_CHUNK_W, B_CHUNK_B, full);
            }
        }
        for (int s = STAGES - 1; s < KC; s++) {
            bar_sync_1_288();
            if (e) {
                int slot = s % STAGES;
                uint32_t full = mb + slot * 8;
                MBAR_EXPECT(full, A_CHUNK_B + B_CHUNK_B);
                bulk_g2s(smb + slot * A_CHUNK_B, Gt + (size_t)s * A_CHUNK_W, A_CHUNK_B, full);
                bulk_g2s(smb + STAGES * A_CHUNK_B + slot * B_CHUNK_B, Bt + (size_t)s * B_CHUNK_W, B_CHUNK_B, full);
            }
        }
        return;
    }

    // ---- math warps (0..7): warp tile 64x64 ----
    const int wm = (warp >> 1) * 64;
    const int wn = (warp & 1) * 64;

    float acc[4][8][4];
    #pragma unroll
    for (int i = 0; i < 4; i++)
        #pragma unroll
        for (int j = 0; j < 8; j++)
            #pragma unroll
            for (int e = 0; e < 4; e++) acc[i][j][e] = 0.f;

    int slot = 0, ph = 0;
    for (int s = 0; s < KC; s++) {
        mbar_wait(mb + slot * 8, ph);
        const uint32_t* As = smw + slot * A_CHUNK_W;
        const uint32_t* Bs = smw + STAGES * A_CHUNK_W + slot * B_CHUNK_W;

        #pragma unroll
        for (int ks = 0; ks < 2; ks++) {
            unsigned af[4][4], bf[8][2];
            int wc = ks * 8 + (lane & 3);
            int r = wm + (lane >> 2);
            #pragma unroll
            for (int i = 0; i < 4; i++) {
                af[i][0] = As[(r + i * 16) * A_PITCH_W + wc];
                af[i][1] = As[(r + i * 16 + 8) * A_PITCH_W + wc];
                af[i][2] = As[(r + i * 16) * A_PITCH_W + wc + 4];
                af[i][3] = As[(r + i * 16 + 8) * A_PITCH_W + wc + 4];
            }
            int bn = wn + (lane >> 2);
            #pragma unroll
            for (int j = 0; j < 8; j++) {
                bf[j][0] = Bs[(bn + j * 8) * B_PITCH_W + wc];
                bf[j][1] = Bs[(bn + j * 8) * B_PITCH_W + wc + 4];
            }
            #pragma unroll
            for (int i = 0; i < 4; i++)
                #pragma unroll
                for (int j = 0; j < 8; j++)
                    mma16(acc[i][j], af[i], bf[j]);
        }
        if (s <= KC - STAGES) bar_arrive_1_288();   // matched with producer syncs
        if (++slot == STAGES) { slot = 0; ph ^= 1; }
    }

    // ---- epilogue: write Y + fused column stats ----
    float* Yrow = g_Y + (size_t)(mt * 256) * NCOLS + h * 128;
    #pragma unroll
    for (int i = 0; i < 4; i++) {
        int r0 = wm + i * 16 + (lane >> 2);
        #pragma unroll
        for (int j = 0; j < 8; j++) {
            int cb = wn + j * 8 + (lane & 3) * 2;
            *(float2*)(Yrow + (size_t)r0 * NCOLS + cb) = make_float2(acc[i][j][0], acc[i][j][1]);
            *(float2*)(Yrow + (size_t)(r0 + 8) * NCOLS + cb) = make_float2(acc[i][j][2], acc[i][j][3]);
        }
    }

    #pragma unroll
    for (int j = 0; j < 8; j++) {
        #pragma unroll
        for (int e = 0; e < 2; e++) {
            float s = 0.f, q = 0.f;
            #pragma unroll
            for (int i = 0; i < 4; i++) {
                float v0 = acc[i][j][e], v1 = acc[i][j][e + 2];
                s += v0 + v1;
                q += v0 * v0 + v1 * v1;
            }
            #pragma unroll
            for (int m = 16; m >= 4; m >>= 1) {
                s += __shfl_xor_sync(0xffffffffu, s, m);
                q += __shfl_xor_sync(0xffffffffu, q, m);
            }
            if ((lane >> 2) == 0) {
                int col = h * 128 + wn + j * 8 + (lane & 3) * 2 + e;
                atomicAdd(&g_sum[col], s);
                atomicAdd(&g_sumsq[col], q);
            }
        }
    }
}

// ---- head: 4 rows per warp-iter, hoisted weights, BN finalize + 1x1 convs ----
#define ROWS_PER_BLOCK 128
__global__ __launch_bounds__(256) void head_kernel(
    const float* __restrict__ gamma, const float* __restrict__ beta,
    const float* __restrict__ w0, const float* __restrict__ b0,
    const float* __restrict__ w1, const float* __restrict__ b1,
    const float* __restrict__ w2, const float* __restrict__ b2,
    const float* __restrict__ w3, const float* __restrict__ b3,
    const float* __restrict__ w4, const float* __restrict__ b4,
    float* __restrict__ out, int N) {
    __shared__ float scm[NCOLS], bim[NCOLS];
    __shared__ float wsm[3 * NCOLS];     // o-major: wsm[o*NCOLS + col]
    __shared__ float bsm[16];
    const int tid = threadIdx.x;
    const int warp = tid >> 5, lane = tid & 31;
    const int n0 = blockIdx.x * ROWS_PER_BLOCK;

    for (int t = tid; t < NCOLS; t += 256) {
        float inv = 1.f / (float)N;
        float mean = g_sum[t] * inv;
        float var = g_sumsq[t] * inv - mean * mean;
        float s = gamma[t] * rsqrtf(var + EPS);
        scm[t] = s;
        bim[t] = beta[t] - mean * s;
        int h = t >> 7, c = t & 127;
        const float* wp; int oc;
        switch (h) {
            case 0: wp = w0; oc = 3; break;
            case 1: wp = w1; oc = 2; break;
            case 2: wp = w2; oc = 1; break;
            case 3: wp = w3; oc = 3; break;
            default: wp = w4; oc = 2; break;
        }
        #pragma unroll 3
        for (int o = 0; o < 3; o++)
            wsm[o * NCOLS + t] = (o < oc) ? wp[c * oc + o] : 0.f;
    }
    if (tid < 11) {
        float bv;
        if (tid < 3) bv = b0[tid];
        else if (tid < 5) bv = b1[tid - 3];
        else if (tid < 6) bv = b2[tid - 5];
        else if (tid < 9) bv = b3[tid - 6];
        else bv = b4[tid - 9];
        bsm[tid] = bv;
    }
    __syncthreads();

    const int base = n0 + warp * 16;
    for (int g = 0; g < 4; g++) {
        int nb = base + g * 4;
        if (nb >= N) break;
        float acc[44];
        #pragma unroll
        for (int k = 0; k < 44; k++) acc[k] = 0.f;

        #define HEAD_ROUND(hh, OCC, OFFS)                                              \
        {                                                                              \
            int cb = hh * 128 + lane * 4;                                              \
            float4 s4 = *(const float4*)(scm + cb);                                    \
            float4 b4v = *(const float4*)(bim + cb);                                   \
            float wl[OCC][4];                                                          \
            _Pragma("unroll")                                                          \
            for (int o = 0; o < OCC; o++)                                              \
                _Pragma("unroll")                                                      \
                for (int j = 0; j < 4; j++)                                            \
                    wl[o][j] = wsm[o * NCOLS + cb + j];                                \
            _Pragma("unroll")                                                          \
            for (int q = 0; q < 4; q++) {                                              \
                int n = nb + q;                                                        \
                if (n < N) {                                                           \
                    float4 v = *(const float4*)(g_Y + (size_t)n * NCOLS + cb);         \
                    float vv[4];                                                       \
                    vv[0] = fmaxf(v.x * s4.x + b4v.x, 0.f);                            \
                    vv[1] = fmaxf(v.y * s4.y + b4v.y, 0.f);                            \
                    vv[2] = fmaxf(v.z * s4.z + b4v.z, 0.f);                            \
                    vv[3] = fmaxf(v.w * s4.w + b4v.w, 0.f);                            \
                    _Pragma("unroll")                                                  \
                    for (int o = 0; o < OCC; o++) {                                    \
                        float t = vv[0] * wl[o][0] + vv[1] * wl[o][1]                  \
                                + vv[2] * wl[o][2] + vv[3] * wl[o][3];                 \
                        acc[q * 11 + OFFS + o] += t;                                   \
                    }                                                                  \
                }                                                                      \
            }                                                                          \
        }
        HEAD_ROUND(0, 3, 0)
        HEAD_ROUND(1, 2, 3)
        HEAD_ROUND(2, 1, 5)
        HEAD_ROUND(3, 3, 6)
        HEAD_ROUND(4, 2, 9)
        #undef HEAD_ROUND

        #pragma unroll
        for (int k = 0; k < 44; k++) {
            #pragma unroll
            for (int m = 16; m >= 1; m >>= 1)
                acc[k] += __shfl_xor_sync(0xffffffffu, acc[k], m);
        }
        #pragma unroll
        for (int q = 0; q < 4; q++) {
            int n = nb + q;
            if (n < N && lane < 11) {
                float val = acc[q * 11];
                #pragma unroll
                for (int o = 1; o < 11; o++)
                    if (lane == o) val = acc[q * 11 + o];
                out[(size_t)n * 11 + lane] = val + bsm[lane];
            }
        }
    }
}

extern "C" void kernel_launch(void* const* d_in, const int* in_sizes, int n_in,
                              void* d_out, int out_size) {
    const float* feats = (const float*)d_in[0];
    const int*   nbr   = (const int*)d_in[1];
    const float* W1    = (const float*)d_in[2];
    float* out = (float*)d_out;

    int N = in_sizes[0] / C;
    int MT = (N + 255) / 256;

    cudaFuncSetAttribute(gemm_kernel, cudaFuncAttributeMaxDynamicSharedMemorySize, GEMM_SMEM);

    int padrows = MT * 256 - N;
    int prep_total = WPREP_TOTAL + 2 * NCOLS + padrows * KC * A_PITCH_W;
    prep_kernel<<<(prep_total + 255) / 256, 256>>>(W1, N, MT);
    gather_kernel<<<(N * K2 + 7) / 8, 256>>>(feats, nbr, N);
    gemm_kernel<<<dim3(H, MT), 288, GEMM_SMEM>>>();
    head_kernel<<<(N + ROWS_PER_BLOCK - 1) / ROWS_PER_BLOCK, 256>>>(
        (const float*)d_in[3], (const float*)d_in[4],
        (const float*)d_in[5], (const float*)d_in[6],
        (const float*)d_in[7], (const float*)d_in[8],
        (const float*)d_in[9], (const float*)d_in[10],
        (const float*)d_in[11], (const float*)d_in[12],
        (const float*)d_in[13], (const float*)d_in[14], out, N);
}

// round 12
// speedup vs baseline: 1.8819x; 1.0375x over previous
#include <cuda_runtime.h>
#include <cuda_fp16.h>
#include <cstdint>

#define C 128
#define K2 9
#define H 5
#define KDIM 1152
#define NCOLS 640
#define MT_MAX 157           // tiles of 256 rows, covers N<=40192
#define MPAD (MT_MAX * 256)
#define KC 36                // K chunks of 32 halfs
#define STAGES 6
#define EPS 1e-5f

// A chunk: 256 rows x 16 words (32 halfs) + 4 pad words -> pitch 20 (conflict-free)
#define A_PITCH_W 20
#define A_CHUNK_W (256 * A_PITCH_W)   // 5120 words
#define A_CHUNK_B (A_CHUNK_W * 4)     // 20480 B
// B chunk: 128 rows(n) x 16 words(k) + 4 pad -> pitch 20
#define B_PITCH_W 20
#define B_CHUNK_W (128 * B_PITCH_W)   // 2560 words
#define B_CHUNK_B (B_CHUNK_W * 4)     // 10240 B
#define GEMM_SMEM (STAGES * (A_CHUNK_B + B_CHUNK_B))   // 184320

// ---- device-global scratch (allocation-free) ----
__device__ uint32_t g_G[(size_t)MT_MAX * KC * A_CHUNK_W];   // fp16 im2col images (~116 MB)
__device__ uint32_t g_Wt[(size_t)H * KC * B_CHUNK_W];       // fp16 weight images (~1.8 MB)
__device__ __half g_Y16[(size_t)MPAD * NCOLS];              // pre-BN activations fp16 (~51.5 MB)
__device__ float g_sum[NCOLS];
__device__ float g_sumsq[NCOLS];

// ---- helpers ----
__device__ __forceinline__ uint32_t pack2(float a, float b) {
    __half2 h = __floats2half2_rn(a, b);
    return *reinterpret_cast<uint32_t*>(&h);
}
__device__ __forceinline__ uint32_t smem_u32(const void* p) {
    uint32_t a;
    asm("{ .reg .u64 t; cvta.to.shared.u64 t, %1; cvt.u32.u64 %0, t; }" : "=r"(a) : "l"(p));
    return a;
}
__device__ __forceinline__ void mma16(float* d, const unsigned* a, const unsigned* b) {
    asm volatile(
        "mma.sync.aligned.m16n8k16.row.col.f32.f16.f16.f32 "
        "{%0,%1,%2,%3}, {%4,%5,%6,%7}, {%8,%9}, {%0,%1,%2,%3};\n"
        : "+f"(d[0]), "+f"(d[1]), "+f"(d[2]), "+f"(d[3])
        : "r"(a[0]), "r"(a[1]), "r"(a[2]), "r"(a[3]),
          "r"(b[0]), "r"(b[1]));
}
__device__ __forceinline__ void bulk_g2s(uint32_t dst, const void* src, uint32_t bytes, uint32_t mbar) {
    asm volatile(
        "cp.async.bulk.shared::cluster.global.mbarrier::complete_tx::bytes [%0], [%1], %2, [%3];"
        :: "r"(dst), "l"(src), "r"(bytes), "r"(mbar) : "memory");
}
#define MBAR_INIT(a, n) asm volatile("mbarrier.init.shared.b64 [%0], %1;" :: "r"(a), "r"(n) : "memory")
#define MBAR_EXPECT(a, n) asm volatile("mbarrier.arrive.expect_tx.shared.b64 _, [%0], %1;" :: "r"(a), "r"(n) : "memory")

__device__ __forceinline__ void mbar_wait(uint32_t mbar, uint32_t parity) {
    asm volatile(
        "{\n\t.reg .pred P1;\n\t"
        "WAIT_LOOP_%=:\n\t"
        "mbarrier.try_wait.parity.acquire.cta.shared::cta.b64 P1, [%0], %1, 0x989680;\n\t"
        "@P1 bra.uni WAIT_DONE_%=;\n\t"
        "bra.uni WAIT_LOOP_%=;\n\t"
        "WAIT_DONE_%=:\n\t}"
        :: "r"(mbar), "r"(parity) : "memory");
}
__device__ __forceinline__ void bar_arrive_1_288() {
    asm volatile("bar.arrive 1, 288;" ::: "memory");
}
__device__ __forceinline__ void bar_sync_1_288() {
    asm volatile("bar.sync 1, 288;" ::: "memory");
}
__device__ __forceinline__ uint32_t elect1() {
    uint32_t p;
    asm volatile("{\n\t.reg .pred p;\n\telect.sync _|p, 0xFFFFFFFF;\n\tselp.b32 %0, 1, 0, p;\n\t}"
                 : "=r"(p));
    return p;
}

// ---- prep: weight pack (fp16 k-pairs, n-major) + stats zero + A-image pad zero ----
#define WPREP_TOTAL (H * 576 * 128)     // one thread per (h, k-pair, n)
__global__ void prep_kernel(const float* __restrict__ W1, int N, int MT) {
    int gi = blockIdx.x * 256 + threadIdx.x;
    if (gi < WPREP_TOTAL) {
        int n = gi & 127;
        int kw = (gi >> 7) % 576;
        int h = gi / (576 * 128);
        int tap = kw >> 6;
        int rem = kw & 63;
        int cin0 = rem * 2;
        const float* p = W1 + (((size_t)h * K2 + tap) * C + cin0) * C + n;
        uint32_t u = pack2(p[0], p[C]);
        int kc = tap * 4 + (rem >> 4);
        int wc = rem & 15;
        g_Wt[((size_t)(h * KC + kc) * 128 + n) * B_PITCH_W + wc] = u;
        return;
    }
    int j = gi - WPREP_TOTAL;
    if (j < 2 * NCOLS) {
        if (j < NCOLS) g_sum[j] = 0.f; else g_sumsq[j - NCOLS] = 0.f;
        return;
    }
    int i = j - 2 * NCOLS;
    int padrows = MT * 256 - N;
    int total = padrows * KC * A_PITCH_W;
    if (i < total && padrows > 0) {
        int kc = i / (padrows * A_PITCH_W);
        int rem = i - kc * padrows * A_PITCH_W;
        int r = (N & 255) + rem / A_PITCH_W;
        int cw = rem % A_PITCH_W;
        g_G[(size_t)((MT - 1) * KC + kc) * A_CHUNK_W + r * A_PITCH_W + cw] = 0u;
    }
}

// ---- gather: im2col rows into fp16 A images ----
__global__ __launch_bounds__(256) void gather_kernel(const float* __restrict__ feats,
                                                     const int* __restrict__ nbr, int N) {
    int w = blockIdx.x * 8 + (threadIdx.x >> 5);
    int lane = threadIdx.x & 31;
    if (w >= N * K2) return;
    int n = w / K2, tap = w - n * K2;
    int idx = __ldg(&nbr[w]);
    float4 v = *(const float4*)(feats + (size_t)idx * C + lane * 4);
    uint2 u = make_uint2(pack2(v.x, v.y), pack2(v.z, v.w));
    int kc = tap * 4 + (lane >> 3);
    size_t addr = ((size_t)((n >> 8) * KC + kc) * 256 + (n & 255)) * A_PITCH_W + (lane & 7) * 2;
    *(uint2*)(g_G + addr) = u;
}

// ---- GEMM: 256x128 CTA tile, fp16 mma.sync, producer warp + named barriers ----
__global__ __launch_bounds__(288, 1) void gemm_kernel() {
    extern __shared__ uint32_t smw[];
    __shared__ __align__(8) unsigned long long mbars[STAGES];

    const int tid = threadIdx.x;
    const int h = blockIdx.x;
    const int mt = blockIdx.y;
    const int warp = tid >> 5, lane = tid & 31;

    uint32_t mb = smem_u32(mbars);
    uint32_t smb = smem_u32(smw);
    if (tid == 0) {
        #pragma unroll
        for (int i = 0; i < STAGES; i++) MBAR_INIT(mb + i * 8, 1);
    }
    __syncthreads();

    const uint32_t* Gt = g_G + (size_t)mt * KC * A_CHUNK_W;
    const uint32_t* Bt = g_Wt + (size_t)h * KC * B_CHUNK_W;

    if (warp == 8) {
        // ---- producer warp ----
        uint32_t e = elect1();
        if (e) {
            #pragma unroll
            for (int s = 0; s < STAGES - 1; s++) {
                uint32_t full = mb + s * 8;
                MBAR_EXPECT(full, A_CHUNK_B + B_CHUNK_B);
                bulk_g2s(smb + s * A_CHUNK_B, Gt + (size_t)s * A_CHUNK_W, A_CHUNK_B, full);
                bulk_g2s(smb + STAGES * A_CHUNK_B + s * B_CHUNK_B, Bt + (size_t)s * B_CHUNK_W, B_CHUNK_B, full);
            }
        }
        for (int s = STAGES - 1; s < KC; s++) {
            bar_sync_1_288();
            if (e) {
                int slot = s % STAGES;
                uint32_t full = mb + slot * 8;
                MBAR_EXPECT(full, A_CHUNK_B + B_CHUNK_B);
                bulk_g2s(smb + slot * A_CHUNK_B, Gt + (size_t)s * A_CHUNK_W, A_CHUNK_B, full);
                bulk_g2s(smb + STAGES * A_CHUNK_B + slot * B_CHUNK_B, Bt + (size_t)s * B_CHUNK_W, B_CHUNK_B, full);
            }
        }
        return;
    }

    // ---- math warps (0..7): warp tile 64x64 ----
    const int wm = (warp >> 1) * 64;
    const int wn = (warp & 1) * 64;

    float acc[4][8][4];
    #pragma unroll
    for (int i = 0; i < 4; i++)
        #pragma unroll
        for (int j = 0; j < 8; j++)
            #pragma unroll
            for (int e = 0; e < 4; e++) acc[i][j][e] = 0.f;

    int slot = 0, ph = 0;
    for (int s = 0; s < KC; s++) {
        mbar_wait(mb + slot * 8, ph);
        const uint32_t* As = smw + slot * A_CHUNK_W;
        const uint32_t* Bs = smw + STAGES * A_CHUNK_W + slot * B_CHUNK_W;

        #pragma unroll
        for (int ks = 0; ks < 2; ks++) {
            unsigned af[4][4], bf[8][2];
            int wc = ks * 8 + (lane & 3);
            int r = wm + (lane >> 2);
            #pragma unroll
            for (int i = 0; i < 4; i++) {
                af[i][0] = As[(r + i * 16) * A_PITCH_W + wc];
                af[i][1] = As[(r + i * 16 + 8) * A_PITCH_W + wc];
                af[i][2] = As[(r + i * 16) * A_PITCH_W + wc + 4];
                af[i][3] = As[(r + i * 16 + 8) * A_PITCH_W + wc + 4];
            }
            int bn = wn + (lane >> 2);
            #pragma unroll
            for (int j = 0; j < 8; j++) {
                bf[j][0] = Bs[(bn + j * 8) * B_PITCH_W + wc];
                bf[j][1] = Bs[(bn + j * 8) * B_PITCH_W + wc + 4];
            }
            #pragma unroll
            for (int i = 0; i < 4; i++)
                #pragma unroll
                for (int j = 0; j < 8; j++)
                    mma16(acc[i][j], af[i], bf[j]);
        }
        if (s <= KC - STAGES) bar_arrive_1_288();   // matched with producer syncs
        if (++slot == STAGES) { slot = 0; ph ^= 1; }
    }

    // ---- epilogue: write fp16 Y + fused column stats ----
    __half* Yrow = g_Y16 + (size_t)(mt * 256) * NCOLS + h * 128;
    #pragma unroll
    for (int i = 0; i < 4; i++) {
        int r0 = wm + i * 16 + (lane >> 2);
        #pragma unroll
        for (int j = 0; j < 8; j++) {
            int cb = wn + j * 8 + (lane & 3) * 2;
            *(uint32_t*)(Yrow + (size_t)r0 * NCOLS + cb) = pack2(acc[i][j][0], acc[i][j][1]);
            *(uint32_t*)(Yrow + (size_t)(r0 + 8) * NCOLS + cb) = pack2(acc[i][j][2], acc[i][j][3]);
        }
    }

    #pragma unroll
    for (int j = 0; j < 8; j++) {
        #pragma unroll
        for (int e = 0; e < 2; e++) {
            float s = 0.f, q = 0.f;
            #pragma unroll
            for (int i = 0; i < 4; i++) {
                float v0 = acc[i][j][e], v1 = acc[i][j][e + 2];
                s += v0 + v1;
                q += v0 * v0 + v1 * v1;
            }
            #pragma unroll
            for (int m = 16; m >= 4; m >>= 1) {
                s += __shfl_xor_sync(0xffffffffu, s, m);
                q += __shfl_xor_sync(0xffffffffu, q, m);
            }
            if ((lane >> 2) == 0) {
                int col = h * 128 + wn + j * 8 + (lane & 3) * 2 + e;
                atomicAdd(&g_sum[col], s);
                atomicAdd(&g_sumsq[col], q);
            }
        }
    }
}

// ---- head: warp-per-row, fp16 Y, BN finalize + 1x1 convs + concat ----
#define ROWS_PER_BLOCK 64
__global__ __launch_bounds__(256) void head_kernel(
    const float* __restrict__ gamma, const float* __restrict__ beta,
    const float* __restrict__ w0, const float* __restrict__ b0,
    const float* __restrict__ w1, const float* __restrict__ b1,
    const float* __restrict__ w2, const float* __restrict__ b2,
    const float* __restrict__ w3, const float* __restrict__ b3,
    const float* __restrict__ w4, const float* __restrict__ b4,
    float* __restrict__ out, int N) {
    __shared__ float scm[NCOLS], bim[NCOLS];
    __shared__ float wsm[3 * NCOLS];     // o-major
    __shared__ float bsm[16];
    const int tid = threadIdx.x;
    const int warp = tid >> 5, lane = tid & 31;
    const int n0 = blockIdx.x * ROWS_PER_BLOCK;

    for (int t = tid; t < NCOLS; t += 256) {
        float inv = 1.f / (float)N;
        float mean = g_sum[t] * inv;
        float var = g_sumsq[t] * inv - mean * mean;
        float s = gamma[t] * rsqrtf(var + EPS);
        scm[t] = s;
        bim[t] = beta[t] - mean * s;
        int h = t >> 7, c = t & 127;
        const float* wp; int oc;
        switch (h) {
            case 0: wp = w0; oc = 3; break;
            case 1: wp = w1; oc = 2; break;
            case 2: wp = w2; oc = 1; break;
            case 3: wp = w3; oc = 3; break;
            default: wp = w4; oc = 2; break;
        }
        #pragma unroll 3
        for (int o = 0; o < 3; o++)
            wsm[o * NCOLS + t] = (o < oc) ? wp[c * oc + o] : 0.f;
    }
    if (tid < 11) {
        float bv;
        if (tid < 3) bv = b0[tid];
        else if (tid < 5) bv = b1[tid - 3];
        else if (tid < 6) bv = b2[tid - 5];
        else if (tid < 9) bv = b3[tid - 6];
        else bv = b4[tid - 9];
        bsm[tid] = bv;
    }
    __syncthreads();

    for (int r = warp; r < ROWS_PER_BLOCK; r += 8) {
        int n = n0 + r;
        if (n >= N) break;
        const __half* Yn = g_Y16 + (size_t)n * NCOLS;
        float acc[11];
        #pragma unroll
        for (int o = 0; o < 11; o++) acc[o] = 0.f;

        #define HEAD_ROUND(hh, OCC, OFFS)                                              \
        {                                                                              \
            int cb = hh * 128 + lane * 4;                                              \
            uint2 raw = *(const uint2*)(Yn + cb);                                      \
            float2 p0 = __half22float2(*(const __half2*)&raw.x);                       \
            float2 p1 = __half22float2(*(const __half2*)&raw.y);                       \
            float4 s4 = *(const float4*)(scm + cb);                                    \
            float4 b4v = *(const float4*)(bim + cb);                                   \
            float vv[4];                                                               \
            vv[0] = fmaxf(p0.x * s4.x + b4v.x, 0.f);                                   \
            vv[1] = fmaxf(p0.y * s4.y + b4v.y, 0.f);                                   \
            vv[2] = fmaxf(p1.x * s4.z + b4v.z, 0.f);                                   \
            vv[3] = fmaxf(p1.y * s4.w + b4v.w, 0.f);                                   \
            _Pragma("unroll")                                                          \
            for (int o = 0; o < OCC; o++) {                                            \
                float t = vv[0] * wsm[o * NCOLS + cb]                                  \
                        + vv[1] * wsm[o * NCOLS + cb + 1]                              \
                        + vv[2] * wsm[o * NCOLS + cb + 2]                              \
                        + vv[3] * wsm[o * NCOLS + cb + 3];                             \
                acc[OFFS + o] += t;                                                    \
            }                                                                          \
        }
        HEAD_ROUND(0, 3, 0)
        HEAD_ROUND(1, 2, 3)
        HEAD_ROUND(2, 1, 5)
        HEAD_ROUND(3, 3, 6)
        HEAD_ROUND(4, 2, 9)
        #undef HEAD_ROUND

        #pragma unroll
        for (int o = 0; o < 11; o++) {
            #pragma unroll
            for (int m = 16; m >= 1; m >>= 1)
                acc[o] += __shfl_xor_sync(0xffffffffu, acc[o], m);
        }
        if (lane < 11) {
            float val = acc[0];
            #pragma unroll
            for (int o = 1; o < 11; o++)
                if (lane == o) val = acc[o];
            out[(size_t)n * 11 + lane] = val + bsm[lane];
        }
    }
}

extern "C" void kernel_launch(void* const* d_in, const int* in_sizes, int n_in,
                              void* d_out, int out_size) {
    const float* feats = (const float*)d_in[0];
    const int*   nbr   = (const int*)d_in[1];
    const float* W1    = (const float*)d_in[2];
    float* out = (float*)d_out;

    int N = in_sizes[0] / C;
    int MT = (N + 255) / 256;

    cudaFuncSetAttribute(gemm_kernel, cudaFuncAttributeMaxDynamicSharedMemorySize, GEMM_SMEM);

    int padrows = MT * 256 - N;
    int prep_total = WPREP_TOTAL + 2 * NCOLS + padrows * KC * A_PITCH_W;
    prep_kernel<<<(prep_total + 255) / 256, 256>>>(W1, N, MT);
    gather_kernel<<<(N * K2 + 7) / 8, 256>>>(feats, nbr, N);
    gemm_kernel<<<dim3(H, MT), 288, GEMM_SMEM>>>();
    head_kernel<<<(N + ROWS_PER_BLOCK - 1) / ROWS_PER_BLOCK, 256>>>(
        (const float*)d_in[3], (const float*)d_in[4],
        (const float*)d_in[5], (const float*)d_in[6],
        (const float*)d_in[7], (const float*)d_in[8],
        (const float*)d_in[9], (const float*)d_in[10],
        (const float*)d_in[11], (const float*)d_in[12],
        (const float*)d_in[13], (const float*)d_in[14], out, N);
}

// round 13
// speedup vs baseline: 1.9001x; 1.0097x over previous
#include <cuda_runtime.h>
#include <cuda_fp16.h>
#include <cstdint>

#define C 128
#define K2 9
#define H 5
#define KDIM 1152
#define NCOLS 640
#define MT_MAX 157           // tiles of 256 rows, covers N<=40192
#define MPAD (MT_MAX * 256)
#define KC 36                // K chunks of 32 halfs
#define STAGES 6
#define EPS 1e-5f

// A chunk: 256 rows x 16 words (32 halfs) + 4 pad words -> pitch 20 (conflict-free)
#define A_PITCH_W 20
#define A_CHUNK_W (256 * A_PITCH_W)   // 5120 words
#define A_CHUNK_B (A_CHUNK_W * 4)     // 20480 B
// B chunk: 128 rows(n) x 16 words(k) + 4 pad -> pitch 20
#define B_PITCH_W 20
#define B_CHUNK_W (128 * B_PITCH_W)   // 2560 words
#define B_CHUNK_B (B_CHUNK_W * 4)     // 10240 B
#define GEMM_SMEM (STAGES * (A_CHUNK_B + B_CHUNK_B))   // 184320

// ---- device-global scratch (allocation-free) ----
__device__ uint32_t g_G[(size_t)MT_MAX * KC * A_CHUNK_W];   // fp16 im2col images (~116 MB)
__device__ uint32_t g_Wt[(size_t)H * KC * B_CHUNK_W];       // fp16 weight images (~1.8 MB)
__device__ __half g_Y16[(size_t)MPAD * NCOLS];              // pre-BN activations fp16 (~51.5 MB)
__device__ float g_sum[NCOLS];
__device__ float g_sumsq[NCOLS];

// ---- helpers ----
__device__ __forceinline__ uint32_t pack2(float a, float b) {
    __half2 h = __floats2half2_rn(a, b);
    return *reinterpret_cast<uint32_t*>(&h);
}
__device__ __forceinline__ uint32_t smem_u32(const void* p) {
    uint32_t a;
    asm("{ .reg .u64 t; cvta.to.shared.u64 t, %1; cvt.u32.u64 %0, t; }" : "=r"(a) : "l"(p));
    return a;
}
__device__ __forceinline__ void mma16(float* d, const unsigned* a, const unsigned* b) {
    asm volatile(
        "mma.sync.aligned.m16n8k16.row.col.f32.f16.f16.f32 "
        "{%0,%1,%2,%3}, {%4,%5,%6,%7}, {%8,%9}, {%0,%1,%2,%3};\n"
        : "+f"(d[0]), "+f"(d[1]), "+f"(d[2]), "+f"(d[3])
        : "r"(a[0]), "r"(a[1]), "r"(a[2]), "r"(a[3]),
          "r"(b[0]), "r"(b[1]));
}
__device__ __forceinline__ void ldsm_x4(unsigned& r0, unsigned& r1, unsigned& r2, unsigned& r3,
                                        uint32_t addr) {
    asm volatile("ldmatrix.sync.aligned.m8n8.x4.shared.b16 {%0,%1,%2,%3}, [%4];"
                 : "=r"(r0), "=r"(r1), "=r"(r2), "=r"(r3) : "r"(addr));
}
__device__ __forceinline__ void bulk_g2s(uint32_t dst, const void* src, uint32_t bytes, uint32_t mbar) {
    asm volatile(
        "cp.async.bulk.shared::cluster.global.mbarrier::complete_tx::bytes [%0], [%1], %2, [%3];"
        :: "r"(dst), "l"(src), "r"(bytes), "r"(mbar) : "memory");
}
#define MBAR_INIT(a, n) asm volatile("mbarrier.init.shared.b64 [%0], %1;" :: "r"(a), "r"(n) : "memory")
#define MBAR_EXPECT(a, n) asm volatile("mbarrier.arrive.expect_tx.shared.b64 _, [%0], %1;" :: "r"(a), "r"(n) : "memory")

__device__ __forceinline__ void mbar_wait(uint32_t mbar, uint32_t parity) {
    asm volatile(
        "{\n\t.reg .pred P1;\n\t"
        "WAIT_LOOP_%=:\n\t"
        "mbarrier.try_wait.parity.acquire.cta.shared::cta.b64 P1, [%0], %1, 0x989680;\n\t"
        "@P1 bra.uni WAIT_DONE_%=;\n\t"
        "bra.uni WAIT_LOOP_%=;\n\t"
        "WAIT_DONE_%=:\n\t}"
        :: "r"(mbar), "r"(parity) : "memory");
}
__device__ __forceinline__ void bar_arrive_1_288() {
    asm volatile("bar.arrive 1, 288;" ::: "memory");
}
__device__ __forceinline__ void bar_sync_1_288() {
    asm volatile("bar.sync 1, 288;" ::: "memory");
}
__device__ __forceinline__ uint32_t elect1() {
    uint32_t p;
    asm volatile("{\n\t.reg .pred p;\n\telect.sync _|p, 0xFFFFFFFF;\n\tselp.b32 %0, 1, 0, p;\n\t}"
                 : "=r"(p));
    return p;
}

// ---- prep: weight pack (fp16 k-pairs, n-major) + stats zero + A-image pad zero ----
#define WPREP_TOTAL (H * 576 * 128)     // one thread per (h, k-pair, n)
__global__ void prep_kernel(const float* __restrict__ W1, int N, int MT) {
    int gi = blockIdx.x * 256 + threadIdx.x;
    if (gi < WPREP_TOTAL) {
        int n = gi & 127;
        int kw = (gi >> 7) % 576;
        int h = gi / (576 * 128);
        int tap = kw >> 6;
        int rem = kw & 63;
        int cin0 = rem * 2;
        const float* p = W1 + (((size_t)h * K2 + tap) * C + cin0) * C + n;
        uint32_t u = pack2(p[0], p[C]);
        int kc = tap * 4 + (rem >> 4);
        int wc = rem & 15;
        g_Wt[((size_t)(h * KC + kc) * 128 + n) * B_PITCH_W + wc] = u;
        return;
    }
    int j = gi - WPREP_TOTAL;
    if (j < 2 * NCOLS) {
        if (j < NCOLS) g_sum[j] = 0.f; else g_sumsq[j - NCOLS] = 0.f;
        return;
    }
    int i = j - 2 * NCOLS;
    int padrows = MT * 256 - N;
    int total = padrows * KC * A_PITCH_W;
    if (i < total && padrows > 0) {
        int kc = i / (padrows * A_PITCH_W);
        int rem = i - kc * padrows * A_PITCH_W;
        int r = (N & 255) + rem / A_PITCH_W;
        int cw = rem % A_PITCH_W;
        g_G[(size_t)((MT - 1) * KC + kc) * A_CHUNK_W + r * A_PITCH_W + cw] = 0u;
    }
}

// ---- gather: im2col rows into fp16 A images ----
__global__ __launch_bounds__(256) void gather_kernel(const float* __restrict__ feats,
                                                     const int* __restrict__ nbr, int N) {
    int w = blockIdx.x * 8 + (threadIdx.x >> 5);
    int lane = threadIdx.x & 31;
    if (w >= N * K2) return;
    int n = w / K2, tap = w - n * K2;
    int idx = __ldg(&nbr[w]);
    float4 v = *(const float4*)(feats + (size_t)idx * C + lane * 4);
    uint2 u = make_uint2(pack2(v.x, v.y), pack2(v.z, v.w));
    int kc = tap * 4 + (lane >> 3);
    size_t addr = ((size_t)((n >> 8) * KC + kc) * 256 + (n & 255)) * A_PITCH_W + (lane & 7) * 2;
    *(uint2*)(g_G + addr) = u;
}

// ---- GEMM: 256x128 CTA tile, fp16 mma.sync, LDSM fragments, producer warp ----
__global__ __launch_bounds__(288, 1) void gemm_kernel() {
    extern __shared__ uint32_t smw[];
    __shared__ __align__(8) unsigned long long mbars[STAGES];

    const int tid = threadIdx.x;
    const int h = blockIdx.x;
    const int mt = blockIdx.y;
    const int warp = tid >> 5, lane = tid & 31;

    uint32_t mb = smem_u32(mbars);
    uint32_t smb = smem_u32(smw);
    if (tid == 0) {
        #pragma unroll
        for (int i = 0; i < STAGES; i++) MBAR_INIT(mb + i * 8, 1);
    }
    __syncthreads();

    const uint32_t* Gt = g_G + (size_t)mt * KC * A_CHUNK_W;
    const uint32_t* Bt = g_Wt + (size_t)h * KC * B_CHUNK_W;

    if (warp == 8) {
        // ---- producer warp ----
        uint32_t e = elect1();
        if (e) {
            #pragma unroll
            for (int s = 0; s < STAGES - 1; s++) {
                uint32_t full = mb + s * 8;
                MBAR_EXPECT(full, A_CHUNK_B + B_CHUNK_B);
                bulk_g2s(smb + s * A_CHUNK_B, Gt + (size_t)s * A_CHUNK_W, A_CHUNK_B, full);
                bulk_g2s(smb + STAGES * A_CHUNK_B + s * B_CHUNK_B, Bt + (size_t)s * B_CHUNK_W, B_CHUNK_B, full);
            }
        }
        for (int s = STAGES - 1; s < KC; s++) {
            bar_sync_1_288();
            if (e) {
                int slot = s % STAGES;
                uint32_t full = mb + slot * 8;
                MBAR_EXPECT(full, A_CHUNK_B + B_CHUNK_B);
                bulk_g2s(smb + slot * A_CHUNK_B, Gt + (size_t)s * A_CHUNK_W, A_CHUNK_B, full);
                bulk_g2s(smb + STAGES * A_CHUNK_B + slot * B_CHUNK_B, Bt + (size_t)s * B_CHUNK_W, B_CHUNK_B, full);
            }
        }
        return;
    }

    // ---- math warps (0..7): warp tile 64x64 ----
    const int wm = (warp >> 1) * 64;
    const int wn = (warp & 1) * 64;

    // per-lane ldmatrix byte offsets (within a chunk)
    // A x4 tiles: (r-lo,k-lo),(r-hi,k-lo),(r-lo,k-hi),(r-hi,k-hi) -> a0..a3
    const uint32_t a_off =
        ((wm + (lane & 7) + ((lane >> 3) & 1) * 8) * A_PITCH_W + (lane >> 4) * 4) * 4;
    // B x4 tiles: (j,k-lo),(j,k-hi),(j+1,k-lo),(j+1,k-hi) -> b[j][0],b[j][1],b[j+1][0],b[j+1][1]
    const uint32_t b_off =
        ((wn + ((lane >> 4) & 1) * 8 + (lane & 7)) * B_PITCH_W + ((lane >> 3) & 1) * 4) * 4;

    float acc[4][8][4];
    #pragma unroll
    for (int i = 0; i < 4; i++)
        #pragma unroll
        for (int j = 0; j < 8; j++)
            #pragma unroll
            for (int e = 0; e < 4; e++) acc[i][j][e] = 0.f;

    int slot = 0, ph = 0;
    for (int s = 0; s < KC; s++) {
        mbar_wait(mb + slot * 8, ph);
        uint32_t Abase = smb + slot * A_CHUNK_B + a_off;
        uint32_t Bbase = smb + STAGES * A_CHUNK_B + slot * B_CHUNK_B + b_off;

        #pragma unroll
        for (int ks = 0; ks < 2; ks++) {
            unsigned af[4][4], bf[8][2];
            #pragma unroll
            for (int i = 0; i < 4; i++)
                ldsm_x4(af[i][0], af[i][1], af[i][2], af[i][3],
                        Abase + (i * 16 * A_PITCH_W + ks * 8) * 4);
            #pragma unroll
            for (int p = 0; p < 4; p++)
                ldsm_x4(bf[p * 2][0], bf[p * 2][1], bf[p * 2 + 1][0], bf[p * 2 + 1][1],
                        Bbase + (p * 16 * B_PITCH_W + ks * 8) * 4);
            #pragma unroll
            for (int i = 0; i < 4; i++)
                #pragma unroll
                for (int j = 0; j < 8; j++)
                    mma16(acc[i][j], af[i], bf[j]);
        }
        if (s <= KC - STAGES) bar_arrive_1_288();   // matched with producer syncs
        if (++slot == STAGES) { slot = 0; ph ^= 1; }
    }

    // ---- epilogue: write fp16 Y + fused column stats ----
    __half* Yrow = g_Y16 + (size_t)(mt * 256) * NCOLS + h * 128;
    #pragma unroll
    for (int i = 0; i < 4; i++) {
        int r0 = wm + i * 16 + (lane >> 2);
        #pragma unroll
        for (int j = 0; j < 8; j++) {
            int cb = wn + j * 8 + (lane & 3) * 2;
            *(uint32_t*)(Yrow + (size_t)r0 * NCOLS + cb) = pack2(acc[i][j][0], acc[i][j][1]);
            *(uint32_t*)(Yrow + (size_t)(r0 + 8) * NCOLS + cb) = pack2(acc[i][j][2], acc[i][j][3]);
        }
    }

    #pragma unroll
    for (int j = 0; j < 8; j++) {
        #pragma unroll
        for (int e = 0; e < 2; e++) {
            float s = 0.f, q = 0.f;
            #pragma unroll
            for (int i = 0; i < 4; i++) {
                float v0 = acc[i][j][e], v1 = acc[i][j][e + 2];
                s += v0 + v1;
                q += v0 * v0 + v1 * v1;
            }
            #pragma unroll
            for (int m = 16; m >= 4; m >>= 1) {
                s += __shfl_xor_sync(0xffffffffu, s, m);
                q += __shfl_xor_sync(0xffffffffu, q, m);
            }
            if ((lane >> 2) == 0) {
                int col = h * 128 + wn + j * 8 + (lane & 3) * 2 + e;
                atomicAdd(&g_sum[col], s);
                atomicAdd(&g_sumsq[col], q);
            }
        }
    }
}

// ---- head: warp-per-row, fp16 Y, BN finalize + 1x1 convs + concat ----
#define ROWS_PER_BLOCK 64
__global__ __launch_bounds__(256) void head_kernel(
    const float* __restrict__ gamma, const float* __restrict__ beta,
    const float* __restrict__ w0, const float* __restrict__ b0,
    const float* __restrict__ w1, const float* __restrict__ b1,
    const float* __restrict__ w2, const float* __restrict__ b2,
    const float* __restrict__ w3, const float* __restrict__ b3,
    const float* __restrict__ w4, const float* __restrict__ b4,
    float* __restrict__ out, int N) {
    __shared__ float scm[NCOLS], bim[NCOLS];
    __shared__ float wsm[3 * NCOLS];     // o-major
    __shared__ float bsm[16];
    const int tid = threadIdx.x;
    const int warp = tid >> 5, lane = tid & 31;
    const int n0 = blockIdx.x * ROWS_PER_BLOCK;

    for (int t = tid; t < NCOLS; t += 256) {
        float inv = 1.f / (float)N;
        float mean = g_sum[t] * inv;
        float var = g_sumsq[t] * inv - mean * mean;
        float s = gamma[t] * rsqrtf(var + EPS);
        scm[t] = s;
        bim[t] = beta[t] - mean * s;
        int h = t >> 7, c = t & 127;
        const float* wp; int oc;
        switch (h) {
            case 0: wp = w0; oc = 3; break;
            case 1: wp = w1; oc = 2; break;
            case 2: wp = w2; oc = 1; break;
            case 3: wp = w3; oc = 3; break;
            default: wp = w4; oc = 2; break;
        }
        #pragma unroll 3
        for (int o = 0; o < 3; o++)
            wsm[o * NCOLS + t] = (o < oc) ? wp[c * oc + o] : 0.f;
    }
    if (tid < 11) {
        float bv;
        if (tid < 3) bv = b0[tid];
        else if (tid < 5) bv = b1[tid - 3];
        else if (tid < 6) bv = b2[tid - 5];
        else if (tid < 9) bv = b3[tid - 6];
        else bv = b4[tid - 9];
        bsm[tid] = bv;
    }
    __syncthreads();

    for (int r = warp; r < ROWS_PER_BLOCK; r += 8) {
        int n = n0 + r;
        if (n >= N) break;
        const __half* Yn = g_Y16 + (size_t)n * NCOLS;
        float acc[11];
        #pragma unroll
        for (int o = 0; o < 11; o++) acc[o] = 0.f;

        #define HEAD_ROUND(hh, OCC, OFFS)                                              \
        {                                                                              \
            int cb = hh * 128 + lane * 4;                                              \
            uint2 raw = *(const uint2*)(Yn + cb);                                      \
            float2 p0 = __half22float2(*(const __half2*)&raw.x);                       \
            float2 p1 = __half22float2(*(const __half2*)&raw.y);                       \
            float4 s4 = *(const float4*)(scm + cb);                                    \
            float4 b4v = *(const float4*)(bim + cb);                                   \
            float vv[4];                                                               \
            vv[0] = fmaxf(p0.x * s4.x + b4v.x, 0.f);                                   \
            vv[1] = fmaxf(p0.y * s4.y + b4v.y, 0.f);                                   \
            vv[2] = fmaxf(p1.x * s4.z + b4v.z, 0.f);                                   \
            vv[3] = fmaxf(p1.y * s4.w + b4v.w, 0.f);                                   \
            _Pragma("unroll")                                                          \
            for (int o = 0; o < OCC; o++) {                                            \
                float t = vv[0] * wsm[o * NCOLS + cb]                                  \
                        + vv[1] * wsm[o * NCOLS + cb + 1]                              \
                        + vv[2] * wsm[o * NCOLS + cb + 2]                              \
                        + vv[3] * wsm[o * NCOLS + cb + 3];                             \
                acc[OFFS + o] += t;                                                    \
            }                                                                          \
        }
        HEAD_ROUND(0, 3, 0)
        HEAD_ROUND(1, 2, 3)
        HEAD_ROUND(2, 1, 5)
        HEAD_ROUND(3, 3, 6)
        HEAD_ROUND(4, 2, 9)
        #undef HEAD_ROUND

        #pragma unroll
        for (int o = 0; o < 11; o++) {
            #pragma unroll
            for (int m = 16; m >= 1; m >>= 1)
                acc[o] += __shfl_xor_sync(0xffffffffu, acc[o], m);
        }
        if (lane < 11) {
            float val = acc[0];
            #pragma unroll
            for (int o = 1; o < 11; o++)
                if (lane == o) val = acc[o];
            out[(size_t)n * 11 + lane] = val + bsm[lane];
        }
    }
}

extern "C" void kernel_launch(void* const* d_in, const int* in_sizes, int n_in,
                              void* d_out, int out_size) {
    const float* feats = (const float*)d_in[0];
    const int*   nbr   = (const int*)d_in[1];
    const float* W1    = (const float*)d_in[2];
    float* out = (float*)d_out;

    int N = in_sizes[0] / C;
    int MT = (N + 255) / 256;

    cudaFuncSetAttribute(gemm_kernel, cudaFuncAttributeMaxDynamicSharedMemorySize, GEMM_SMEM);

    int padrows = MT * 256 - N;
    int prep_total = WPREP_TOTAL + 2 * NCOLS + padrows * KC * A_PITCH_W;
    prep_kernel<<<(prep_total + 255) / 256, 256>>>(W1, N, MT);
    gather_kernel<<<(N * K2 + 7) / 8, 256>>>(feats, nbr, N);
    gemm_kernel<<<dim3(H, MT), 288, GEMM_SMEM>>>();
    head_kernel<<<(N + ROWS_PER_BLOCK - 1) / ROWS_PER_BLOCK, 256>>>(
        (const float*)d_in[3], (const float*)d_in[4],
        (const float*)d_in[5], (const float*)d_in[6],
        (const float*)d_in[7], (const float*)d_in[8],
        (const float*)d_in[9], (const float*)d_in[10],
        (const float*)d_in[11], (const float*)d_in[12],
        (const float*)d_in[13], (const float*)d_in[14], out, N);
}

// round 15
// speedup vs baseline: 1.9088x; 1.0046x over previous
#include <cuda_runtime.h>
#include <cuda_fp16.h>
#include <cstdint>

#define C 128
#define K2 9
#define H 5
#define KDIM 1152
#define NCOLS 640
#define MT_MAX 157           // tiles of 256 rows, covers N<=40192
#define MPAD (MT_MAX * 256)
#define KC 36                // K chunks of 32 halfs
#define STAGES 6
#define EPS 1e-5f

// A chunk: 256 rows x 16 words (32 halfs) + 4 pad words -> pitch 20 (conflict-free)
#define A_PITCH_W 20
#define A_CHUNK_W (256 * A_PITCH_W)   // 5120 words
#define A_CHUNK_B (A_CHUNK_W * 4)     // 20480 B
// B chunk: 128 rows(n) x 16 words(k) + 4 pad -> pitch 20
#define B_PITCH_W 20
#define B_CHUNK_W (128 * B_PITCH_W)   // 2560 words
#define B_CHUNK_B (B_CHUNK_W * 4)     // 10240 B
#define GEMM_SMEM (STAGES * (A_CHUNK_B + B_CHUNK_B))   // 184320

// ---- device-global scratch (allocation-free) ----
__device__ uint32_t g_G[(size_t)MT_MAX * KC * A_CHUNK_W];   // fp16 im2col images (~116 MB)
__device__ uint32_t g_Wt[(size_t)H * KC * B_CHUNK_W];       // fp16 weight images (~1.8 MB)
__device__ uint32_t g_F16[(size_t)MPAD * C / 2];            // fp16 feats, packed half2 (10.3 MB)
__device__ __half g_Y16[(size_t)MPAD * NCOLS];              // pre-BN activations fp16 (~51.5 MB)
__device__ float g_sum[NCOLS];
__device__ float g_sumsq[NCOLS];

// ---- helpers ----
__device__ __forceinline__ uint32_t pack2(float a, float b) {
    __half2 h = __floats2half2_rn(a, b);
    return *reinterpret_cast<uint32_t*>(&h);
}
__device__ __forceinline__ uint32_t smem_u32(const void* p) {
    uint32_t a;
    asm("{ .reg .u64 t; cvta.to.shared.u64 t, %1; cvt.u32.u64 %0, t; }" : "=r"(a) : "l"(p));
    return a;
}
__device__ __forceinline__ void mma16(float* d, const unsigned* a, const unsigned* b) {
    asm volatile(
        "mma.sync.aligned.m16n8k16.row.col.f32.f16.f16.f32 "
        "{%0,%1,%2,%3}, {%4,%5,%6,%7}, {%8,%9}, {%0,%1,%2,%3};\n"
        : "+f"(d[0]), "+f"(d[1]), "+f"(d[2]), "+f"(d[3])
        : "r"(a[0]), "r"(a[1]), "r"(a[2]), "r"(a[3]),
          "r"(b[0]), "r"(b[1]));
}
__device__ __forceinline__ void ldsm_x4(unsigned& r0, unsigned& r1, unsigned& r2, unsigned& r3,
                                        uint32_t addr) {
    asm volatile("ldmatrix.sync.aligned.m8n8.x4.shared.b16 {%0,%1,%2,%3}, [%4];"
                 : "=r"(r0), "=r"(r1), "=r"(r2), "=r"(r3) : "r"(addr));
}
__device__ __forceinline__ void bulk_g2s(uint32_t dst, const void* src, uint32_t bytes, uint32_t mbar) {
    asm volatile(
        "cp.async.bulk.shared::cluster.global.mbarrier::complete_tx::bytes [%0], [%1], %2, [%3];"
        :: "r"(dst), "l"(src), "r"(bytes), "r"(mbar) : "memory");
}
#define MBAR_INIT(a, n) asm volatile("mbarrier.init.shared.b64 [%0], %1;" :: "r"(a), "r"(n) : "memory")
#define MBAR_EXPECT(a, n) asm volatile("mbarrier.arrive.expect_tx.shared.b64 _, [%0], %1;" :: "r"(a), "r"(n) : "memory")

__device__ __forceinline__ void mbar_wait(uint32_t mbar, uint32_t parity) {
    asm volatile(
        "{\n\t.reg .pred P1;\n\t"
        "WAIT_LOOP_%=:\n\t"
        "mbarrier.try_wait.parity.acquire.cta.shared::cta.b64 P1, [%0], %1, 0x989680;\n\t"
        "@P1 bra.uni WAIT_DONE_%=;\n\t"
        "bra.uni WAIT_LOOP_%=;\n\t"
        "WAIT_DONE_%=:\n\t}"
        :: "r"(mbar), "r"(parity) : "memory");
}
__device__ __forceinline__ void bar_arrive_1_288() {
    asm volatile("bar.arrive 1, 288;" ::: "memory");
}
__device__ __forceinline__ void bar_sync_1_288() {
    asm volatile("bar.sync 1, 288;" ::: "memory");
}
__device__ __forceinline__ uint32_t elect1() {
    uint32_t p;
    asm volatile("{\n\t.reg .pred p;\n\telect.sync _|p, 0xFFFFFFFF;\n\tselp.b32 %0, 1, 0, p;\n\t}"
                 : "=r"(p));
    return p;
}

// ---- prep: weight pack + stats zero + A-image pad zero + feats fp16 convert ----
#define WPREP_TOTAL (H * 576 * 128)     // one thread per (h, k-pair, n)
__global__ void prep_kernel(const float* __restrict__ W1, const float* __restrict__ feats,
                            int N, int MT) {
    int gi = blockIdx.x * 256 + threadIdx.x;
    if (gi < WPREP_TOTAL) {
        int n = gi & 127;
        int kw = (gi >> 7) % 576;
        int h = gi / (576 * 128);
        int tap = kw >> 6;
        int rem = kw & 63;
        int cin0 = rem * 2;
        const float* p = W1 + (((size_t)h * K2 + tap) * C + cin0) * C + n;
        uint32_t u = pack2(p[0], p[C]);
        int kc = tap * 4 + (rem >> 4);
        int wc = rem & 15;
        g_Wt[((size_t)(h * KC + kc) * 128 + n) * B_PITCH_W + wc] = u;
        return;
    }
    int j = gi - WPREP_TOTAL;
    if (j < 2 * NCOLS) {
        if (j < NCOLS) g_sum[j] = 0.f; else g_sumsq[j - NCOLS] = 0.f;
        return;
    }
    int i = j - 2 * NCOLS;
    int padrows = MT * 256 - N;
    int padtotal = padrows * KC * A_PITCH_W;
    if (i < padtotal) {
        int kc = i / (padrows * A_PITCH_W);
        int rem = i - kc * padrows * A_PITCH_W;
        int r = (N & 255) + rem / A_PITCH_W;
        int cw = rem % A_PITCH_W;
        g_G[(size_t)((MT - 1) * KC + kc) * A_CHUNK_W + r * A_PITCH_W + cw] = 0u;
        return;
    }
    int f = i - padtotal;                // feats convert: one thread per 4 floats
    if (f < N * 32) {
        float4 v = *(const float4*)(feats + (size_t)f * 4);
        uint2 u = make_uint2(pack2(v.x, v.y), pack2(v.z, v.w));
        *(uint2*)(g_F16 + (size_t)f * 2) = u;
    }
}

// ---- gather: im2col rows (fp16 source) into fp16 A images ----
__global__ __launch_bounds__(256) void gather_kernel(const int* __restrict__ nbr, int N) {
    int w = blockIdx.x * 8 + (threadIdx.x >> 5);
    int lane = threadIdx.x & 31;
    if (w >= N * K2) return;
    int n = w / K2, tap = w - n * K2;
    int idx = __ldg(&nbr[w]);
    uint2 u = *(const uint2*)(g_F16 + (size_t)idx * 64 + lane * 2);
    int kc = tap * 4 + (lane >> 3);
    size_t addr = ((size_t)((n >> 8) * KC + kc) * 256 + (n & 255)) * A_PITCH_W + (lane & 7) * 2;
    *(uint2*)(g_G + addr) = u;
}

// ---- GEMM: 256x128 CTA tile, fp16 mma.sync, LDSM fragments, producer warp ----
// (byte-for-byte the round-13 structure; do not restructure the barrier loops)
__global__ __launch_bounds__(288, 1) void gemm_kernel() {
    extern __shared__ uint32_t smw[];
    __shared__ __align__(8) unsigned long long mbars[STAGES];

    const int tid = threadIdx.x;
    const int h = blockIdx.x;
    const int mt = blockIdx.y;
    const int warp = tid >> 5, lane = tid & 31;

    uint32_t mb = smem_u32(mbars);
    uint32_t smb = smem_u32(smw);
    if (tid == 0) {
        #pragma unroll
        for (int i = 0; i < STAGES; i++) MBAR_INIT(mb + i * 8, 1);
    }
    __syncthreads();

    const uint32_t* Gt = g_G + (size_t)mt * KC * A_CHUNK_W;
    const uint32_t* Bt = g_Wt + (size_t)h * KC * B_CHUNK_W;

    if (warp == 8) {
        // ---- producer warp ----
        uint32_t e = elect1();
        if (e) {
            #pragma unroll
            for (int s = 0; s < STAGES - 1; s++) {
                uint32_t full = mb + s * 8;
                MBAR_EXPECT(full, A_CHUNK_B + B_CHUNK_B);
                bulk_g2s(smb + s * A_CHUNK_B, Gt + (size_t)s * A_CHUNK_W, A_CHUNK_B, full);
                bulk_g2s(smb + STAGES * A_CHUNK_B + s * B_CHUNK_B, Bt + (size_t)s * B_CHUNK_W, B_CHUNK_B, full);
            }
        }
        for (int s = STAGES - 1; s < KC; s++) {
            bar_sync_1_288();
            if (e) {
                int slot = s % STAGES;
                uint32_t full = mb + slot * 8;
                MBAR_EXPECT(full, A_CHUNK_B + B_CHUNK_B);
                bulk_g2s(smb + slot * A_CHUNK_B, Gt + (size_t)s * A_CHUNK_W, A_CHUNK_B, full);
                bulk_g2s(smb + STAGES * A_CHUNK_B + slot * B_CHUNK_B, Bt + (size_t)s * B_CHUNK_W, B_CHUNK_B, full);
            }
        }
        return;
    }

    // ---- math warps (0..7): warp tile 64x64 ----
    const int wm = (warp >> 1) * 64;
    const int wn = (warp & 1) * 64;

    // per-lane ldmatrix byte offsets (within a chunk)
    const uint32_t a_off =
        ((wm + (lane & 7) + ((lane >> 3) & 1) * 8) * A_PITCH_W + (lane >> 4) * 4) * 4;
    const uint32_t b_off =
        ((wn + ((lane >> 4) & 1) * 8 + (lane & 7)) * B_PITCH_W + ((lane >> 3) & 1) * 4) * 4;

    float acc[4][8][4];
    #pragma unroll
    for (int i = 0; i < 4; i++)
        #pragma unroll
        for (int j = 0; j < 8; j++)
            #pragma unroll
            for (int e = 0; e < 4; e++) acc[i][j][e] = 0.f;

    int slot = 0, ph = 0;
    for (int s = 0; s < KC; s++) {
        mbar_wait(mb + slot * 8, ph);
        uint32_t Abase = smb + slot * A_CHUNK_B + a_off;
        uint32_t Bbase = smb + STAGES * A_CHUNK_B + slot * B_CHUNK_B + b_off;

        #pragma unroll
        for (int ks = 0; ks < 2; ks++) {
            unsigned af[4][4], bf[8][2];
            #pragma unroll
            for (int i = 0; i < 4; i++)
                ldsm_x4(af[i][0], af[i][1], af[i][2], af[i][3],
                        Abase + (i * 16 * A_PITCH_W + ks * 8) * 4);
            #pragma unroll
            for (int p = 0; p < 4; p++)
                ldsm_x4(bf[p * 2][0], bf[p * 2][1], bf[p * 2 + 1][0], bf[p * 2 + 1][1],
                        Bbase + (p * 16 * B_PITCH_W + ks * 8) * 4);
            #pragma unroll
            for (int i = 0; i < 4; i++)
                #pragma unroll
                for (int j = 0; j < 8; j++)
                    mma16(acc[i][j], af[i], bf[j]);
        }
        if (s <= KC - STAGES) bar_arrive_1_288();   // matched with producer syncs
        if (++slot == STAGES) { slot = 0; ph ^= 1; }
    }

    // ---- epilogue: write fp16 Y + fused column stats ----
    __half* Yrow = g_Y16 + (size_t)(mt * 256) * NCOLS + h * 128;
    #pragma unroll
    for (int i = 0; i < 4; i++) {
        int r0 = wm + i * 16 + (lane >> 2);
        #pragma unroll
        for (int j = 0; j < 8; j++) {
            int cb = wn + j * 8 + (lane & 3) * 2;
            *(uint32_t*)(Yrow + (size_t)r0 * NCOLS + cb) = pack2(acc[i][j][0], acc[i][j][1]);
            *(uint32_t*)(Yrow + (size_t)(r0 + 8) * NCOLS + cb) = pack2(acc[i][j][2], acc[i][j][3]);
        }
    }

    #pragma unroll
    for (int j = 0; j < 8; j++) {
        #pragma unroll
        for (int e = 0; e < 2; e++) {
            float s = 0.f, q = 0.f;
            #pragma unroll
            for (int i = 0; i < 4; i++) {
                float v0 = acc[i][j][e], v1 = acc[i][j][e + 2];
                s += v0 + v1;
                q += v0 * v0 + v1 * v1;
            }
            #pragma unroll
            for (int m = 16; m >= 4; m >>= 1) {
                s += __shfl_xor_sync(0xffffffffu, s, m);
                q += __shfl_xor_sync(0xffffffffu, q, m);
            }
            if ((lane >> 2) == 0) {
                int col = h * 128 + wn + j * 8 + (lane & 3) * 2 + e;
                atomicAdd(&g_sum[col], s);
                atomicAdd(&g_sumsq[col], q);
            }
        }
    }
}

// ---- head: 2 rows per warp-iter (MLP x2), fp16 Y, BN finalize + 1x1 convs ----
#define ROWS_PER_BLOCK 64
__global__ __launch_bounds__(256) void head_kernel(
    const float* __restrict__ gamma, const float* __restrict__ beta,
    const float* __restrict__ w0, const float* __restrict__ b0,
    const float* __restrict__ w1, const float* __restrict__ b1,
    const float* __restrict__ w2, const float* __restrict__ b2,
    const float* __restrict__ w3, const float* __restrict__ b3,
    const float* __restrict__ w4, const float* __restrict__ b4,
    float* __restrict__ out, int N) {
    __shared__ float scm[NCOLS], bim[NCOLS];
    __shared__ float wsm[3 * NCOLS];     // o-major
    __shared__ float bsm[16];
    const int tid = threadIdx.x;
    const int warp = tid >> 5, lane = tid & 31;
    const int n0 = blockIdx.x * ROWS_PER_BLOCK;

    for (int t = tid; t < NCOLS; t += 256) {
        float inv = 1.f / (float)N;
        float mean = g_sum[t] * inv;
        float var = g_sumsq[t] * inv - mean * mean;
        float s = gamma[t] * rsqrtf(var + EPS);
        scm[t] = s;
        bim[t] = beta[t] - mean * s;
        int h = t >> 7, c = t & 127;
        const float* wp; int oc;
        switch (h) {
            case 0: wp = w0; oc = 3; break;
            case 1: wp = w1; oc = 2; break;
            case 2: wp = w2; oc = 1; break;
            case 3: wp = w3; oc = 3; break;
            default: wp = w4; oc = 2; break;
        }
        #pragma unroll 3
        for (int o = 0; o < 3; o++)
            wsm[o * NCOLS + t] = (o < oc) ? wp[c * oc + o] : 0.f;
    }
    if (tid < 11) {
        float bv;
        if (tid < 3) bv = b0[tid];
        else if (tid < 5) bv = b1[tid - 3];
        else if (tid < 6) bv = b2[tid - 5];
        else if (tid < 9) bv = b3[tid - 6];
        else bv = b4[tid - 9];
        bsm[tid] = bv;
    }
    __syncthreads();

    for (int r = warp; r < ROWS_PER_BLOCK; r += 16) {
        int nA = n0 + r;
        int nB = n0 + r + 8;
        bool vA = nA < N, vB = nB < N;
        if (!vA) break;
        const __half* YA = g_Y16 + (size_t)nA * NCOLS;
        const __half* YB = g_Y16 + (size_t)nB * NCOLS;
        float accA[11], accB[11];
        #pragma unroll
        for (int o = 0; o < 11; o++) { accA[o] = 0.f; accB[o] = 0.f; }

        #define HEAD_ROUND2(hh, OCC, OFFS)                                             \
        {                                                                              \
            int cb = hh * 128 + lane * 4;                                              \
            uint2 rawA = *(const uint2*)(YA + cb);                                     \
            uint2 rawB = vB ? *(const uint2*)(YB + cb) : make_uint2(0u, 0u);           \
            float4 s4 = *(const float4*)(scm + cb);                                    \
            float4 b4v = *(const float4*)(bim + cb);                                   \
            float2 a0 = __half22float2(*(const __half2*)&rawA.x);                      \
            float2 a1 = __half22float2(*(const __half2*)&rawA.y);                      \
            float2 c0 = __half22float2(*(const __half2*)&rawB.x);                      \
            float2 c1 = __half22float2(*(const __half2*)&rawB.y);                      \
            float vvA[4], vvB[4];                                                      \
            vvA[0] = fmaxf(a0.x * s4.x + b4v.x, 0.f);                                  \
            vvA[1] = fmaxf(a0.y * s4.y + b4v.y, 0.f);                                  \
            vvA[2] = fmaxf(a1.x * s4.z + b4v.z, 0.f);                                  \
            vvA[3] = fmaxf(a1.y * s4.w + b4v.w, 0.f);                                  \
            vvB[0] = fmaxf(c0.x * s4.x + b4v.x, 0.f);                                  \
            vvB[1] = fmaxf(c0.y * s4.y + b4v.y, 0.f);                                  \
            vvB[2] = fmaxf(c1.x * s4.z + b4v.z, 0.f);                                  \
            vvB[3] = fmaxf(c1.y * s4.w + b4v.w, 0.f);                                  \
            _Pragma("unroll")                                                          \
            for (int o = 0; o < OCC; o++) {                                            \
                float w0_ = wsm[o * NCOLS + cb];                                       \
                float w1_ = wsm[o * NCOLS + cb + 1];                                   \
                float w2_ = wsm[o * NCOLS + cb + 2];                                   \
                float w3_ = wsm[o * NCOLS + cb + 3];                                   \
                accA[OFFS + o] += vvA[0] * w0_ + vvA[1] * w1_                          \
                                + vvA[2] * w2_ + vvA[3] * w3_;                         \
                accB[OFFS + o] += vvB[0] * w0_ + vvB[1] * w1_                          \
                                + vvB[2] * w2_ + vvB[3] * w3_;                         \
            }                                                                          \
        }
        HEAD_ROUND2(0, 3, 0)
        HEAD_ROUND2(1, 2, 3)
        HEAD_ROUND2(2, 1, 5)
        HEAD_ROUND2(3, 3, 6)
        HEAD_ROUND2(4, 2, 9)
        #undef HEAD_ROUND2

        #pragma unroll
        for (int o = 0; o < 11; o++) {
            #pragma unroll
            for (int m = 16; m >= 1; m >>= 1) {
                accA[o] += __shfl_xor_sync(0xffffffffu, accA[o], m);
                accB[o] += __shfl_xor_sync(0xffffffffu, accB[o], m);
            }
        }
        if (lane < 11) {
            float valA = accA[0], valB = accB[0];
            #pragma unroll
            for (int o = 1; o < 11; o++) {
                if (lane == o) { valA = accA[o]; valB = accB[o]; }
            }
            out[(size_t)nA * 11 + lane] = valA + bsm[lane];
            if (vB) out[(size_t)nB * 11 + lane] = valB + bsm[lane];
        }
    }
}

extern "C" void kernel_launch(void* const* d_in, const int* in_sizes, int n_in,
                              void* d_out, int out_size) {
    const float* feats = (const float*)d_in[0];
    const int*   nbr   = (const int*)d_in[1];
    const float* W1    = (const float*)d_in[2];
    float* out = (float*)d_out;

    int N = in_sizes[0] / C;
    int MT = (N + 255) / 256;

    cudaFuncSetAttribute(gemm_kernel, cudaFuncAttributeMaxDynamicSharedMemorySize, GEMM_SMEM);

    int padrows = MT * 256 - N;
    int prep_total = WPREP_TOTAL + 2 * NCOLS + padrows * KC * A_PITCH_W + N * 32;
    prep_kernel<<<(prep_total + 255) / 256, 256>>>(W1, feats, N, MT);
    gather_kernel<<<(N * K2 + 7) / 8, 256>>>(nbr, N);
    gemm_kernel<<<dim3(H, MT), 288, GEMM_SMEM>>>();
    head_kernel<<<(N + ROWS_PER_BLOCK - 1) / ROWS_PER_BLOCK, 256>>>(
        (const float*)d_in[3], (const float*)d_in[4],
        (const float*)d_in[5], (const float*)d_in[6],
        (const float*)d_in[7], (const float*)d_in[8],
        (const float*)d_in[9], (const float*)d_in[10],
        (const float*)d_in[11], (const float*)d_in[12],
        (const float*)d_in[13], (const float*)d_in[14], out, N);
}

// round 17
// speedup vs baseline: 2.0305x; 1.0638x over previous
#include <cuda_runtime.h>
#include <cuda_fp16.h>
#include <cstdint>

#define C 128
#define K2 9
#define H 5
#define KDIM 1152
#define NCOLS 640
#define MT_MAX 157           // tiles of 256 rows, covers N<=40192
#define MPAD (MT_MAX * 256)
#define KC 36                // K chunks of 32 halfs
#define STAGES 6
#define EPS 1e-5f
#define NMATH_WARPS 16
#define GTHREADS (NMATH_WARPS * 32 + 32)   // 544: 16 math warps + 1 producer warp

// A chunk: 256 rows x 16 words (32 halfs) + 4 pad words -> pitch 20 (conflict-free)
#define A_PITCH_W 20
#define A_CHUNK_W (256 * A_PITCH_W)   // 5120 words
#define A_CHUNK_B (A_CHUNK_W * 4)     // 20480 B
// B chunk: 128 rows(n) x 16 words(k) + 4 pad -> pitch 20
#define B_PITCH_W 20
#define B_CHUNK_W (128 * B_PITCH_W)   // 2560 words
#define B_CHUNK_B (B_CHUNK_W * 4)     // 10240 B
#define GEMM_SMEM (STAGES * (A_CHUNK_B + B_CHUNK_B))   // 184320

// ---- device-global scratch (allocation-free) ----
__device__ uint32_t g_G[(size_t)MT_MAX * KC * A_CHUNK_W];   // fp16 im2col images (~116 MB)
__device__ uint32_t g_Wt[(size_t)H * KC * B_CHUNK_W];       // fp16 weight images (~1.8 MB)
__device__ uint32_t g_F16[(size_t)MPAD * C / 2];            // fp16 feats, packed half2 (10.3 MB)
__device__ __half g_Y16[(size_t)MPAD * NCOLS];              // pre-BN activations fp16 (~51.5 MB)
__device__ float g_sum[NCOLS];
__device__ float g_sumsq[NCOLS];

// ---- helpers ----
__device__ __forceinline__ uint32_t pack2(float a, float b) {
    __half2 h = __floats2half2_rn(a, b);
    return *reinterpret_cast<uint32_t*>(&h);
}
__device__ __forceinline__ uint32_t smem_u32(const void* p) {
    uint32_t a;
    asm("{ .reg .u64 t; cvta.to.shared.u64 t, %1; cvt.u32.u64 %0, t; }" : "=r"(a) : "l"(p));
    return a;
}
__device__ __forceinline__ void mma16(float* d, const unsigned* a, const unsigned* b) {
    asm volatile(
        "mma.sync.aligned.m16n8k16.row.col.f32.f16.f16.f32 "
        "{%0,%1,%2,%3}, {%4,%5,%6,%7}, {%8,%9}, {%0,%1,%2,%3};\n"
        : "+f"(d[0]), "+f"(d[1]), "+f"(d[2]), "+f"(d[3])
        : "r"(a[0]), "r"(a[1]), "r"(a[2]), "r"(a[3]),
          "r"(b[0]), "r"(b[1]));
}
__device__ __forceinline__ void ldsm_x4(unsigned& r0, unsigned& r1, unsigned& r2, unsigned& r3,
                                        uint32_t addr) {
    asm volatile("ldmatrix.sync.aligned.m8n8.x4.shared.b16 {%0,%1,%2,%3}, [%4];"
                 : "=r"(r0), "=r"(r1), "=r"(r2), "=r"(r3) : "r"(addr));
}
__device__ __forceinline__ void bulk_g2s(uint32_t dst, const void* src, uint32_t bytes, uint32_t mbar) {
    asm volatile(
        "cp.async.bulk.shared::cluster.global.mbarrier::complete_tx::bytes [%0], [%1], %2, [%3];"
        :: "r"(dst), "l"(src), "r"(bytes), "r"(mbar) : "memory");
}
#define MBAR_INIT(a, n) asm volatile("mbarrier.init.shared.b64 [%0], %1;" :: "r"(a), "r"(n) : "memory")
#define MBAR_EXPECT(a, n) asm volatile("mbarrier.arrive.expect_tx.shared.b64 _, [%0], %1;" :: "r"(a), "r"(n) : "memory")
#define MBAR_ARRIVE(a) asm volatile("mbarrier.arrive.shared.b64 _, [%0];" :: "r"(a) : "memory")

__device__ __forceinline__ void mbar_wait(uint32_t mbar, uint32_t parity) {
    asm volatile(
        "{\n\t.reg .pred P1;\n\t"
        "WAIT_LOOP_%=:\n\t"
        "mbarrier.try_wait.parity.acquire.cta.shared::cta.b64 P1, [%0], %1, 0x989680;\n\t"
        "@P1 bra.uni WAIT_DONE_%=;\n\t"
        "bra.uni WAIT_LOOP_%=;\n\t"
        "WAIT_DONE_%=:\n\t}"
        :: "r"(mbar), "r"(parity) : "memory");
}
__device__ __forceinline__ void mbar_wait_relaxed(uint32_t mbar, uint32_t parity) {
    asm volatile(
        "{\n\t.reg .pred P1;\n\t"
        "WAIT_LOOP_%=:\n\t"
        "mbarrier.try_wait.parity.relaxed.cta.shared::cta.b64 P1, [%0], %1, 0x989680;\n\t"
        "@P1 bra.uni WAIT_DONE_%=;\n\t"
        "bra.uni WAIT_LOOP_%=;\n\t"
        "WAIT_DONE_%=:\n\t}"
        :: "r"(mbar), "r"(parity) : "memory");
}
__device__ __forceinline__ uint32_t elect1() {
    uint32_t p;
    asm volatile("{\n\t.reg .pred p;\n\telect.sync _|p, 0xFFFFFFFF;\n\tselp.b32 %0, 1, 0, p;\n\t}"
                 : "=r"(p));
    return p;
}

// ---- prep: weight pack + stats zero + A-image pad zero + feats fp16 convert ----
#define WPREP_TOTAL (H * 576 * 128)     // one thread per (h, k-pair, n)
__global__ void prep_kernel(const float* __restrict__ W1, const float* __restrict__ feats,
                            int N, int MT) {
    int gi = blockIdx.x * 256 + threadIdx.x;
    if (gi < WPREP_TOTAL) {
        int n = gi & 127;
        int kw = (gi >> 7) % 576;
        int h = gi / (576 * 128);
        int tap = kw >> 6;
        int rem = kw & 63;
        int cin0 = rem * 2;
        const float* p = W1 + (((size_t)h * K2 + tap) * C + cin0) * C + n;
        uint32_t u = pack2(p[0], p[C]);
        int kc = tap * 4 + (rem >> 4);
        int wc = rem & 15;
        g_Wt[((size_t)(h * KC + kc) * 128 + n) * B_PITCH_W + wc] = u;
        return;
    }
    int j = gi - WPREP_TOTAL;
    if (j < 2 * NCOLS) {
        if (j < NCOLS) g_sum[j] = 0.f; else g_sumsq[j - NCOLS] = 0.f;
        return;
    }
    int i = j - 2 * NCOLS;
    int padrows = MT * 256 - N;
    int padtotal = padrows * KC * A_PITCH_W;
    if (i < padtotal) {
        int kc = i / (padrows * A_PITCH_W);
        int rem = i - kc * padrows * A_PITCH_W;
        int r = (N & 255) + rem / A_PITCH_W;
        int cw = rem % A_PITCH_W;
        g_G[(size_t)((MT - 1) * KC + kc) * A_CHUNK_W + r * A_PITCH_W + cw] = 0u;
        return;
    }
    int f = i - padtotal;                // feats convert: one thread per 4 floats
    if (f < N * 32) {
        float4 v = *(const float4*)(feats + (size_t)f * 4);
        uint2 u = make_uint2(pack2(v.x, v.y), pack2(v.z, v.w));
        *(uint2*)(g_F16 + (size_t)f * 2) = u;
    }
}

// ---- gather: im2col rows (fp16 source) into fp16 A images ----
__global__ __launch_bounds__(256) void gather_kernel(const int* __restrict__ nbr, int N) {
    int w = blockIdx.x * 8 + (threadIdx.x >> 5);
    int lane = threadIdx.x & 31;
    if (w >= N * K2) return;
    int n = w / K2, tap = w - n * K2;
    int idx = __ldg(&nbr[w]);
    uint2 u = *(const uint2*)(g_F16 + (size_t)idx * 64 + lane * 2);
    int kc = tap * 4 + (lane >> 3);
    size_t addr = ((size_t)((n >> 8) * KC + kc) * 256 + (n & 255)) * A_PITCH_W + (lane & 7) * 2;
    *(uint2*)(g_G + addr) = u;
}

// ---- GEMM: 256x128 CTA tile, 16 math warps (64x32) + producer warp ----
// full/empty mbarrier-pair pipeline (canonical pattern; no named barriers)
__global__ __launch_bounds__(GTHREADS, 1) void gemm_kernel() {
    extern __shared__ uint32_t smw[];
    __shared__ __align__(8) unsigned long long mbars[2 * STAGES]; // full[0..5], empty[6..11]

    const int tid = threadIdx.x;
    const int h = blockIdx.x;
    const int mt = blockIdx.y;
    const int warp = tid >> 5, lane = tid & 31;

    uint32_t mb = smem_u32(mbars);
    uint32_t smb = smem_u32(smw);
    if (tid == 0) {
        #pragma unroll
        for (int i = 0; i < STAGES; i++) {
            MBAR_INIT(mb + i * 8, 1);                       // full: producer expect_tx
            MBAR_INIT(mb + (STAGES + i) * 8, NMATH_WARPS);  // empty: one arrive per math warp
        }
    }
    __syncthreads();

    const uint32_t* Gt = g_G + (size_t)mt * KC * A_CHUNK_W;
    const uint32_t* Bt = g_Wt + (size_t)h * KC * B_CHUNK_W;

    if (warp == NMATH_WARPS) {
        // ---- producer warp: uniform loop; first STAGES empty-waits pass by parity ----
        uint32_t e = elect1();
        if (e) {
            int slot = 0, eph = 1;
            for (int s = 0; s < KC; s++) {
                mbar_wait_relaxed(mb + (STAGES + slot) * 8, eph);
                uint32_t full = mb + slot * 8;
                MBAR_EXPECT(full, A_CHUNK_B + B_CHUNK_B);
                bulk_g2s(smb + slot * A_CHUNK_B, Gt + (size_t)s * A_CHUNK_W, A_CHUNK_B, full);
                bulk_g2s(smb + STAGES * A_CHUNK_B + slot * B_CHUNK_B,
                         Bt + (size_t)s * B_CHUNK_W, B_CHUNK_B, full);
                if (++slot == STAGES) { slot = 0; eph ^= 1; }
            }
        }
        return;
    }

    // ---- math warps (0..15): warp tile 64x32 ----
    const int wm = (warp >> 2) * 64;    // 0,64,128,192
    const int wn = (warp & 3) * 32;     // 0,32,64,96

    // per-lane ldmatrix byte offsets (within a chunk)
    const uint32_t a_off =
        ((wm + (lane & 7) + ((lane >> 3) & 1) * 8) * A_PITCH_W + (lane >> 4) * 4) * 4;
    const uint32_t b_off =
        ((wn + ((lane >> 4) & 1) * 8 + (lane & 7)) * B_PITCH_W + ((lane >> 3) & 1) * 4) * 4;

    float acc[4][4][4];
    #pragma unroll
    for (int i = 0; i < 4; i++)
        #pragma unroll
        for (int j = 0; j < 4; j++)
            #pragma unroll
            for (int e = 0; e < 4; e++) acc[i][j][e] = 0.f;

    int slot = 0, ph = 0;
    for (int s = 0; s < KC; s++) {
        mbar_wait(mb + slot * 8, ph);
        uint32_t Abase = smb + slot * A_CHUNK_B + a_off;
        uint32_t Bbase = smb + STAGES * A_CHUNK_B + slot * B_CHUNK_B + b_off;

        #pragma unroll
        for (int ks = 0; ks < 2; ks++) {
            unsigned af[4][4], bf[4][2];
            #pragma unroll
            for (int i = 0; i < 4; i++)
                ldsm_x4(af[i][0], af[i][1], af[i][2], af[i][3],
                        Abase + (i * 16 * A_PITCH_W + ks * 8) * 4);
            #pragma unroll
            for (int p = 0; p < 2; p++)
                ldsm_x4(bf[p * 2][0], bf[p * 2][1], bf[p * 2 + 1][0], bf[p * 2 + 1][1],
                        Bbase + (p * 16 * B_PITCH_W + ks * 8) * 4);
            #pragma unroll
            for (int i = 0; i < 4; i++)
                #pragma unroll
                for (int j = 0; j < 4; j++)
                    mma16(acc[i][j], af[i], bf[j]);
        }
        if (lane == 0) MBAR_ARRIVE(mb + (STAGES + slot) * 8);   // release slot
        if (++slot == STAGES) { slot = 0; ph ^= 1; }
    }

    // ---- epilogue: write fp16 Y + fused column stats ----
    __half* Yrow = g_Y16 + (size_t)(mt * 256) * NCOLS + h * 128;
    #pragma unroll
    for (int i = 0; i < 4; i++) {
        int r0 = wm + i * 16 + (lane >> 2);
        #pragma unroll
        for (int j = 0; j < 4; j++) {
            int cb = wn + j * 8 + (lane & 3) * 2;
            *(uint32_t*)(Yrow + (size_t)r0 * NCOLS + cb) = pack2(acc[i][j][0], acc[i][j][1]);
            *(uint32_t*)(Yrow + (size_t)(r0 + 8) * NCOLS + cb) = pack2(acc[i][j][2], acc[i][j][3]);
        }
    }

    #pragma unroll
    for (int j = 0; j < 4; j++) {
        #pragma unroll
        for (int e = 0; e < 2; e++) {
            float s = 0.f, q = 0.f;
            #pragma unroll
            for (int i = 0; i < 4; i++) {
                float v0 = acc[i][j][e], v1 = acc[i][j][e + 2];
                s += v0 + v1;
                q += v0 * v0 + v1 * v1;
            }
            #pragma unroll
            for (int m = 16; m >= 4; m >>= 1) {
                s += __shfl_xor_sync(0xffffffffu, s, m);
                q += __shfl_xor_sync(0xffffffffu, q, m);
            }
            if ((lane >> 2) == 0) {
                int col = h * 128 + wn + j * 8 + (lane & 3) * 2 + e;
                atomicAdd(&g_sum[col], s);
                atomicAdd(&g_sumsq[col], q);
            }
        }
    }
}

// ---- head: 2 rows per warp-iter (MLP x2), fp16 Y, BN finalize + 1x1 convs ----
#define ROWS_PER_BLOCK 64
__global__ __launch_bounds__(256) void head_kernel(
    const float* __restrict__ gamma, const float* __restrict__ beta,
    const float* __restrict__ w0, const float* __restrict__ b0,
    const float* __restrict__ w1, const float* __restrict__ b1,
    const float* __restrict__ w2, const float* __restrict__ b2,
    const float* __restrict__ w3, const float* __restrict__ b3,
    const float* __restrict__ w4, const float* __restrict__ b4,
    float* __restrict__ out, int N) {
    __shared__ float scm[NCOLS], bim[NCOLS];
    __shared__ float wsm[3 * NCOLS];     // o-major
    __shared__ float bsm[16];
    const int tid = threadIdx.x;
    const int warp = tid >> 5, lane = tid & 31;
    const int n0 = blockIdx.x * ROWS_PER_BLOCK;

    for (int t = tid; t < NCOLS; t += 256) {
        float inv = 1.f / (float)N;
        float mean = g_sum[t] * inv;
        float var = g_sumsq[t] * inv - mean * mean;
        float s = gamma[t] * rsqrtf(var + EPS);
        scm[t] = s;
        bim[t] = beta[t] - mean * s;
        int h = t >> 7, c = t & 127;
        const float* wp; int oc;
        switch (h) {
            case 0: wp = w0; oc = 3; break;
            case 1: wp = w1; oc = 2; break;
            case 2: wp = w2; oc = 1; break;
            case 3: wp = w3; oc = 3; break;
            default: wp = w4; oc = 2; break;
        }
        #pragma unroll 3
        for (int o = 0; o < 3; o++)
            wsm[o * NCOLS + t] = (o < oc) ? wp[c * oc + o] : 0.f;
    }
    if (tid < 11) {
        float bv;
        if (tid < 3) bv = b0[tid];
        else if (tid < 5) bv = b1[tid - 3];
        else if (tid < 6) bv = b2[tid - 5];
        else if (tid < 9) bv = b3[tid - 6];
        else bv = b4[tid - 9];
        bsm[tid] = bv;
    }
    __syncthreads();

    for (int r = warp; r < ROWS_PER_BLOCK; r += 16) {
        int nA = n0 + r;
        int nB = n0 + r + 8;
        bool vA = nA < N, vB = nB < N;
        if (!vA) break;
        const __half* YA = g_Y16 + (size_t)nA * NCOLS;
        const __half* YB = g_Y16 + (size_t)nB * NCOLS;
        float accA[11], accB[11];
        #pragma unroll
        for (int o = 0; o < 11; o++) { accA[o] = 0.f; accB[o] = 0.f; }

        #define HEAD_ROUND2(hh, OCC, OFFS)                                             \
        {                                                                              \
            int cb = hh * 128 + lane * 4;                                              \
            uint2 rawA = *(const uint2*)(YA + cb);                                     \
            uint2 rawB = vB ? *(const uint2*)(YB + cb) : make_uint2(0u, 0u);           \
            float4 s4 = *(const float4*)(scm + cb);                                    \
            float4 b4v = *(const float4*)(bim + cb);                                   \
            float2 a0 = __half22float2(*(const __half2*)&rawA.x);                      \
            float2 a1 = __half22float2(*(const __half2*)&rawA.y);                      \
            float2 c0 = __half22float2(*(const __half2*)&rawB.x);                      \
            float2 c1 = __half22float2(*(const __half2*)&rawB.y);                      \
            float vvA[4], vvB[4];                                                      \
            vvA[0] = fmaxf(a0.x * s4.x + b4v.x, 0.f);                                  \
            vvA[1] = fmaxf(a0.y * s4.y + b4v.y, 0.f);                                  \
            vvA[2] = fmaxf(a1.x * s4.z + b4v.z, 0.f);                                  \
            vvA[3] = fmaxf(a1.y * s4.w + b4v.w, 0.f);                                  \
            vvB[0] = fmaxf(c0.x * s4.x + b4v.x, 0.f);                                  \
            vvB[1] = fmaxf(c0.y * s4.y + b4v.y, 0.f);                                  \
            vvB[2] = fmaxf(c1.x * s4.z + b4v.z, 0.f);                                  \
            vvB[3] = fmaxf(c1.y * s4.w + b4v.w, 0.f);                                  \
            _Pragma("unroll")                                                          \
            for (int o = 0; o < OCC; o++) {                                            \
                float w0_ = wsm[o * NCOLS + cb];                                       \
                float w1_ = wsm[o * NCOLS + cb + 1];                                   \
                float w2_ = wsm[o * NCOLS + cb + 2];                                   \
                float w3_ = wsm[o * NCOLS + cb + 3];                                   \
                accA[OFFS + o] += vvA[0] * w0_ + vvA[1] * w1_                          \
                                + vvA[2] * w2_ + vvA[3] * w3_;                         \
                accB[OFFS + o] += vvB[0] * w0_ + vvB[1] * w1_                          \
                                + vvB[2] * w2_ + vvB[3] * w3_;                         \
            }                                                                          \
        }
        HEAD_ROUND2(0, 3, 0)
        HEAD_ROUND2(1, 2, 3)
        HEAD_ROUND2(2, 1, 5)
        HEAD_ROUND2(3, 3, 6)
        HEAD_ROUND2(4, 2, 9)
        #undef HEAD_ROUND2

        #pragma unroll
        for (int o = 0; o < 11; o++) {
            #pragma unroll
            for (int m = 16; m >= 1; m >>= 1) {
                accA[o] += __shfl_xor_sync(0xffffffffu, accA[o], m);
                accB[o] += __shfl_xor_sync(0xffffffffu, accB[o], m);
            }
        }
        if (lane < 11) {
            float valA = accA[0], valB = accB[0];
            #pragma unroll
            for (int o = 1; o < 11; o++) {
                if (lane == o) { valA = accA[o]; valB = accB[o]; }
            }
            out[(size_t)nA * 11 + lane] = valA + bsm[lane];
            if (vB) out[(size_t)nB * 11 + lane] = valB + bsm[lane];
        }
    }
}

extern "C" void kernel_launch(void* const* d_in, const int* in_sizes, int n_in,
                              void* d_out, int out_size) {
    const float* feats = (const float*)d_in[0];
    const int*   nbr   = (const int*)d_in[1];
    const float* W1    = (const float*)d_in[2];
    float* out = (float*)d_out;

    int N = in_sizes[0] / C;
    int MT = (N + 255) / 256;

    cudaFuncSetAttribute(gemm_kernel, cudaFuncAttributeMaxDynamicSharedMemorySize, GEMM_SMEM);

    int padrows = MT * 256 - N;
    int prep_total = WPREP_TOTAL + 2 * NCOLS + padrows * KC * A_PITCH_W + N * 32;
    prep_kernel<<<(prep_total + 255) / 256, 256>>>(W1, feats, N, MT);
    gather_kernel<<<(N * K2 + 7) / 8, 256>>>(nbr, N);
    gemm_kernel<<<dim3(H, MT), GTHREADS, GEMM_SMEM>>>();
    head_kernel<<<(N + ROWS_PER_BLOCK - 1) / ROWS_PER_BLOCK, 256>>>(
        (const float*)d_in[3], (const float*)d_in[4],
        (const float*)d_in[5], (const float*)d_in[6],
        (const float*)d_in[7], (const float*)d_in[8],
        (const float*)d_in[9], (const float*)d_in[10],
        (const float*)d_in[11], (const float*)d_in[12],
        (const float*)d_in[13], (const float*)d_in[14], out, N);
}